// round 12
// baseline (speedup 1.0000x reference)
#include <cuda_runtime.h>
#include <cuda_fp16.h>
#include <math.h>
#include <stdint.h>

#define SEQ 4096
#define DIM 1280
#define NH 20
#define HD 64
#define FFNDIM 5120
#define SEGLEN 512
#define QKVN 3840

// ---------------- scratch (no allocations allowed) ----------------
__device__ __half g_xln[SEQ * DIM];
__device__ __half g_qkv[(size_t)SEQ * QKVN];
__device__ __half g_attnh[SEQ * DIM];
__device__ float  g_h[SEQ * DIM];
__device__ __half g_yln[SEQ * DIM];
__device__ __half g_mid[(size_t)SEQ * FFNDIM];
__device__ __half g_wqkvt[(size_t)QKVN * DIM];
__device__ float  g_bqkv[QKVN];
__device__ __half g_wot[DIM * DIM];
__device__ __half g_wf1t[(size_t)FFNDIM * DIM];
__device__ __half g_wf2t[(size_t)DIM * FFNDIM];

// ---------------- helpers ----------------
__device__ __forceinline__ float f2tf_f(float x) {
    uint32_t u;
    asm("cvt.rna.tf32.f32 %0, %1;" : "=r"(u) : "f"(x));
    return __uint_as_float(u);
}

__device__ __forceinline__ void mma_f16(float* d, const uint32_t* a,
                                        const uint32_t* b) {
    asm volatile(
        "mma.sync.aligned.m16n8k16.row.col.f32.f16.f16.f32 "
        "{%0,%1,%2,%3}, {%4,%5,%6,%7}, {%8,%9}, {%0,%1,%2,%3};"
        : "+f"(d[0]), "+f"(d[1]), "+f"(d[2]), "+f"(d[3])
        : "r"(a[0]), "r"(a[1]), "r"(a[2]), "r"(a[3]),
          "r"(b[0]), "r"(b[1]));
}

__device__ __forceinline__ void mma_tf32(float* d, const uint32_t* a,
                                         const uint32_t* b) {
    asm volatile(
        "mma.sync.aligned.m16n8k8.row.col.f32.tf32.tf32.f32 "
        "{%0,%1,%2,%3}, {%4,%5,%6,%7}, {%8,%9}, {%0,%1,%2,%3};"
        : "+f"(d[0]), "+f"(d[1]), "+f"(d[2]), "+f"(d[3])
        : "r"(a[0]), "r"(a[1]), "r"(a[2]), "r"(a[3]),
          "r"(b[0]), "r"(b[1]));
}

__device__ __forceinline__ uint32_t smem_u32(const void* p) {
    uint32_t a;
    asm("{ .reg .u64 t; cvta.to.shared.u64 t, %1; cvt.u32.u64 %0, t; }" : "=r"(a) : "l"(p));
    return a;
}
#define CP_ASYNC16(s, g) \
    asm volatile("cp.async.cg.shared.global [%0], [%1], 16;" :: "r"(s), "l"(g))
#define CP_COMMIT() asm volatile("cp.async.commit_group;" ::: "memory")
#define CP_WAIT2() asm volatile("cp.async.wait_group 2;" ::: "memory")

#define LDSM_X4(r0, r1, r2, r3, addr)                                        \
    asm volatile("ldmatrix.sync.aligned.m8n8.x4.shared.b16 {%0,%1,%2,%3}, [%4];" \
        : "=r"(r0), "=r"(r1), "=r"(r2), "=r"(r3) : "r"(addr))
#define LDSM_X2(r0, r1, addr)                                                \
    asm volatile("ldmatrix.sync.aligned.m8n8.x2.shared.b16 {%0,%1}, [%2];"   \
        : "=r"(r0), "=r"(r1) : "r"(addr))

// ---------------- transpose to half ----------------
__global__ void transpose_k(const float* __restrict__ in, __half* __restrict__ out,
                            int R, int C, int ldo) {
    __shared__ float t[32][33];
    int c = blockIdx.x * 32 + threadIdx.x;
    int r = blockIdx.y * 32 + threadIdx.y;
#pragma unroll
    for (int j = 0; j < 32; j += 8)
        t[threadIdx.y + j][threadIdx.x] = in[(size_t)(r + j) * C + c];
    __syncthreads();
    int oc = blockIdx.y * 32 + threadIdx.x;
    int orr = blockIdx.x * 32 + threadIdx.y;
#pragma unroll
    for (int j = 0; j < 32; j += 8)
        out[(size_t)(orr + j) * ldo + oc] = __float2half(t[threadIdx.x][threadIdx.y + j]);
}

// ---------------- fused QKV bias ----------------
__global__ void qkvbias_k(const float* __restrict__ bq, const float* __restrict__ bv,
                          float* __restrict__ out) {
    int i = blockIdx.x * 256 + threadIdx.x;
    float v = 0.f;
    if (i < DIM) v = bq[i];
    else if (i >= 2 * DIM) v = bv[i - 2 * DIM];
    out[i] = v;
}

// ---------------- LayerNorm (half output) ----------------
__global__ void ln_kernel(const float* __restrict__ x, const float* __restrict__ g,
                          const float* __restrict__ b, __half* __restrict__ y) {
    int row = blockIdx.x;
    const float* xr = x + (size_t)row * DIM;
    float v[5];
    float s = 0.f, sq = 0.f;
#pragma unroll
    for (int i = 0; i < 5; i++) {
        v[i] = xr[threadIdx.x + i * 256];
        s += v[i];
        sq += v[i] * v[i];
    }
    __shared__ float red[64];
#pragma unroll
    for (int o = 16; o > 0; o >>= 1) {
        s += __shfl_xor_sync(0xFFFFFFFFu, s, o);
        sq += __shfl_xor_sync(0xFFFFFFFFu, sq, o);
    }
    int w = threadIdx.x >> 5, l = threadIdx.x & 31;
    if (l == 0) { red[w] = s; red[w + 8] = sq; }
    __syncthreads();
    if (threadIdx.x < 32) {
        float ss = (threadIdx.x < 8) ? red[threadIdx.x] : 0.f;
        float qq = (threadIdx.x < 8) ? red[threadIdx.x + 8] : 0.f;
#pragma unroll
        for (int o = 4; o > 0; o >>= 1) {
            ss += __shfl_xor_sync(0xFFFFFFFFu, ss, o);
            qq += __shfl_xor_sync(0xFFFFFFFFu, qq, o);
        }
        if (threadIdx.x == 0) { red[32] = ss; red[33] = qq; }
    }
    __syncthreads();
    float mu  = red[32] * (1.f / DIM);
    float var = red[33] * (1.f / DIM) - mu * mu;
    float inv = rsqrtf(var + 1e-5f);
    __half* yr = y + (size_t)row * DIM;
#pragma unroll
    for (int i = 0; i < 5; i++) {
        int c = threadIdx.x + i * 256;
        yr[c] = __float2half((v[i] - mu) * inv * g[c] + b[c]);
    }
}

// ---------------- fp16 mma GEMM, cp.async 4-stage + ldmatrix ----------------
#define EPI_NONE 0
#define EPI_BIAS 1
#define EPI_GELU 2
#define EPI_BIAS_RES 3

#define BK 32                           // halves per K chunk
#define PWH 40                          // pitch in halves (80 B/row)
#define A_HALVES (128 * PWH)            // 5120 halves
#define A_BYTES (A_HALVES * 2)          // 10240
#define STAGE_BYTES (2 * A_BYTES)       // 20480
#define GEMM_DSMEM (4 * STAGE_BYTES)    // 81920

template <int EPI, int OUTH>
__global__ __launch_bounds__(256, 2) void mma_gemm(
    const __half* __restrict__ A, const __half* __restrict__ Bt,
    const float* __restrict__ bias, const float* __restrict__ res,
    void* __restrict__ Cv, int Ntot, int K) {
    extern __shared__ __align__(16) char smc[];
    uint32_t smb = smem_u32(smc);

    int tid = threadIdx.x;
    int wid = tid >> 5, lane = tid & 31;
    int warp_m = wid & 1;
    int warp_n = wid >> 1;
    int g = lane >> 2, c = lane & 3;
    int br = blockIdx.y * 128, bc = blockIdx.x * 128;

    const __half* Abase = A + (size_t)br * K;
    const __half* Bbase = Bt + (size_t)bc * K;

    const int NIT = K / BK;

    // per-thread ldmatrix base offsets (bytes, within stage)
    uint32_t a_off = (uint32_t)(warp_m * 64 + (lane & 15)) * (PWH * 2) + ((lane >> 4) << 4);
    uint32_t b_off = A_BYTES + (uint32_t)(warp_n * 32 + (lane & 7)) * (PWH * 2) + (((lane >> 3) & 1) << 4);

    float acc[4][4][4];
#pragma unroll
    for (int i = 0; i < 4; i++)
#pragma unroll
        for (int j = 0; j < 4; j++)
#pragma unroll
            for (int u = 0; u < 4; u++) acc[i][j][u] = 0.f;

#define ISSUE_STAGE(st)                                                       \
    do {                                                                      \
        int _k0 = (st) * BK;                                                  \
        uint32_t _sa = smb + ((st) & 3) * STAGE_BYTES;                        \
        uint32_t _sb = _sa + A_BYTES;                                         \
        _Pragma("unroll")                                                     \
        for (int _i = 0; _i < 2; _i++) {                                      \
            int _s = tid + _i * 256;                                          \
            int _row = _s >> 2, _f4 = _s & 3;                                 \
            uint32_t _so = (uint32_t)(_row * (PWH * 2) + _f4 * 16);           \
            CP_ASYNC16(_sa + _so, Abase + (size_t)_row * K + _k0 + _f4 * 8);  \
            CP_ASYNC16(_sb + _so, Bbase + (size_t)_row * K + _k0 + _f4 * 8);  \
        }                                                                     \
    } while (0)

    ISSUE_STAGE(0);
    CP_COMMIT();
    ISSUE_STAGE(1);
    CP_COMMIT();
    ISSUE_STAGE(2);
    CP_COMMIT();

    for (int it = 0; it < NIT; it++) {
        CP_WAIT2();
        __syncthreads();
        if (it + 3 < NIT) ISSUE_STAGE(it + 3);
        CP_COMMIT();

        uint32_t sbase = smb + (it & 3) * STAGE_BYTES;
        uint32_t abase = sbase + a_off;
        uint32_t bbase = sbase + b_off;
#pragma unroll
        for (int kk = 0; kk < 2; kk++) {
            uint32_t koff = kk * 32;
            uint32_t af[4][4], bf[4][2];
#pragma unroll
            for (int mt = 0; mt < 4; mt++)
                LDSM_X4(af[mt][0], af[mt][1], af[mt][2], af[mt][3],
                        abase + (uint32_t)mt * 16 * (PWH * 2) + koff);
#pragma unroll
            for (int nt = 0; nt < 4; nt++)
                LDSM_X2(bf[nt][0], bf[nt][1],
                        bbase + (uint32_t)nt * 8 * (PWH * 2) + koff);
#pragma unroll
            for (int mt = 0; mt < 4; mt++)
#pragma unroll
                for (int nt = 0; nt < 4; nt++)
                    mma_f16(acc[mt][nt], af[mt], bf[nt]);
        }
        __syncthreads();
    }

    // epilogue
#pragma unroll
    for (int mt = 0; mt < 4; mt++) {
#pragma unroll
        for (int nt = 0; nt < 4; nt++) {
            int col = bc + warp_n * 32 + nt * 8 + c * 2;
#pragma unroll
            for (int half = 0; half < 2; half++) {
                int row = br + warp_m * 64 + mt * 16 + g + half * 8;
                float x0 = acc[mt][nt][half * 2 + 0];
                float x1 = acc[mt][nt][half * 2 + 1];
                if (EPI == EPI_BIAS || EPI == EPI_GELU || EPI == EPI_BIAS_RES) {
                    x0 += bias[col];
                    x1 += bias[col + 1];
                }
                if (EPI == EPI_GELU) {
                    x0 = 0.5f * x0 * (1.f + erff(x0 * 0.70710678118654752f));
                    x1 = 0.5f * x1 * (1.f + erff(x1 * 0.70710678118654752f));
                }
                if (EPI == EPI_BIAS_RES) {
                    float2 r2 = *(const float2*)(res + (size_t)row * Ntot + col);
                    x0 += r2.x;
                    x1 += r2.y;
                }
                if (OUTH) {
                    __half2* Ch = (__half2*)Cv;
                    Ch[((size_t)row * Ntot + col) >> 1] = __floats2half2_rn(x0, x1);
                } else {
                    float* Cf = (float*)Cv;
                    *(float2*)(Cf + (size_t)row * Ntot + col) = make_float2(x0, x1);
                }
            }
        }
    }
}

// ---------------- tensor-core block-diagonal attention (half in/out) ----------------
#define SP 33
#define QPITCH 68
#define VPITCH 132
#define ASM_Q (512 * SP)
#define ASM_KV (ASM_Q + 32 * QPITCH)
#define ATTN_SMEM_FLOATS (ASM_KV + 128 * QPITCH)

__global__ __launch_bounds__(256) void attn_kernel(
    const __half* __restrict__ Q, const __half* __restrict__ Kg,
    const __half* __restrict__ V, __half* __restrict__ O, int ldq) {
    extern __shared__ float sm[];
    float* scoresT = sm;
    float* Qs = sm + ASM_Q;
    float* KV = sm + ASM_KV;
    uint32_t* scoresT_u = (uint32_t*)scoresT;
    const uint32_t* Qs_u = (const uint32_t*)Qs;
    const uint32_t* KV_u = (const uint32_t*)KV;

    int tid = threadIdx.x;
    int wid = tid >> 5, lane = tid & 31;
    int g = lane >> 2, c = lane & 3;
    int qt = blockIdx.x;
    int hh = blockIdx.y;
    int sg = blockIdx.z;
    int qbase = sg * SEGLEN + qt * 32;
    int kbase = sg * SEGLEN;
    int colbase = hh * HD;

    {
        int r = tid >> 3, f8 = tid & 7;
        uint4 raw = *(const uint4*)(Q + (size_t)(qbase + r) * ldq + colbase + f8 * 8);
        const __half2* hp = (const __half2*)&raw;
        float* dst = &Qs[r * QPITCH + f8 * 8];
#pragma unroll
        for (int j = 0; j < 4; j++) {
            float2 f = __half22float2(hp[j]);
            dst[2 * j] = f.x * 0.125f;
            dst[2 * j + 1] = f.y * 0.125f;
        }
    }

    // ---- Phase A: S = Q @ K^T ----
    for (int kc = 0; kc < 4; kc++) {
        __syncthreads();
#pragma unroll
        for (int i = 0; i < 4; i++) {
            int s = tid + i * 256;
            int r = s >> 3, f8 = s & 7;
            uint4 raw = *(const uint4*)(Kg + (size_t)(kbase + kc * 128 + r) * ldq + colbase + f8 * 8);
            const __half2* hp = (const __half2*)&raw;
            float* dst = &KV[r * QPITCH + f8 * 8];
#pragma unroll
            for (int j = 0; j < 4; j++) {
                float2 f = __half22float2(hp[j]);
                dst[2 * j] = f.x;
                dst[2 * j + 1] = f.y;
            }
        }
        __syncthreads();

        float accS[2][2][4];
#pragma unroll
        for (int mt = 0; mt < 2; mt++)
#pragma unroll
            for (int nt = 0; nt < 2; nt++)
#pragma unroll
                for (int u = 0; u < 4; u++) accS[mt][nt][u] = 0.f;

#pragma unroll
        for (int ks = 0; ks < 8; ks++) {
            int k0 = ks * 8;
            uint32_t qa[2][4];
#pragma unroll
            for (int mt = 0; mt < 2; mt++) {
                int rm = mt * 16 + g;
                qa[mt][0] = Qs_u[rm * QPITCH + k0 + c];
                qa[mt][1] = Qs_u[(rm + 8) * QPITCH + k0 + c];
                qa[mt][2] = Qs_u[rm * QPITCH + k0 + c + 4];
                qa[mt][3] = Qs_u[(rm + 8) * QPITCH + k0 + c + 4];
            }
#pragma unroll
            for (int nt = 0; nt < 2; nt++) {
                int rk = wid * 16 + nt * 8 + g;
                uint32_t kb[2];
                kb[0] = KV_u[rk * QPITCH + k0 + c];
                kb[1] = KV_u[rk * QPITCH + k0 + c + 4];
#pragma unroll
                for (int mt = 0; mt < 2; mt++)
                    mma_tf32(accS[mt][nt], qa[mt], kb);
            }
        }
#pragma unroll
        for (int mt = 0; mt < 2; mt++)
#pragma unroll
            for (int nt = 0; nt < 2; nt++) {
                int keyg = kc * 128 + wid * 16 + nt * 8 + 2 * c;
                int q0 = mt * 16 + g;
                scoresT[keyg * SP + q0]           = accS[mt][nt][0];
                scoresT[(keyg + 1) * SP + q0]     = accS[mt][nt][1];
                scoresT[keyg * SP + q0 + 8]       = accS[mt][nt][2];
                scoresT[(keyg + 1) * SP + q0 + 8] = accS[mt][nt][3];
            }
    }
    __syncthreads();

    // ---- softmax ----
    {
        int w = wid, l = lane;
        for (int qi = 0; qi < 4; qi++) {
            int q = w + qi * 8;
            float vals[16];
            float m = -1e30f;
#pragma unroll
            for (int s = 0; s < 16; s++) {
                vals[s] = scoresT[(l + s * 32) * SP + q];
                m = fmaxf(m, vals[s]);
            }
#pragma unroll
            for (int o = 16; o > 0; o >>= 1) m = fmaxf(m, __shfl_xor_sync(0xFFFFFFFFu, m, o));
            float sum = 0.f;
#pragma unroll
            for (int s = 0; s < 16; s++) {
                float e = __expf(vals[s] - m);
                vals[s] = e;
                sum += e;
            }
#pragma unroll
            for (int o = 16; o > 0; o >>= 1) sum += __shfl_xor_sync(0xFFFFFFFFu, sum, o);
            float r = 1.f / sum;
#pragma unroll
            for (int s = 0; s < 16; s++)
                scoresT[(l + s * 32) * SP + q] = f2tf_f(vals[s] * r);
        }
    }

    // ---- Phase C: O = P @ V ----
    int mhalf = wid & 1;
    int dq = wid >> 1;
    int q0 = mhalf * 16, d0 = dq * 16;
    float accO[2][4];
#pragma unroll
    for (int nt = 0; nt < 2; nt++)
#pragma unroll
        for (int u = 0; u < 4; u++) accO[nt][u] = 0.f;

    for (int kc = 0; kc < 4; kc++) {
        __syncthreads();
#pragma unroll
        for (int i = 0; i < 4; i++) {
            int s = tid + i * 256;
            int r = s >> 3, f8 = s & 7;
            uint4 raw = *(const uint4*)(V + (size_t)(kbase + kc * 128 + r) * ldq + colbase + f8 * 8);
            const __half2* hp = (const __half2*)&raw;
            int d = f8 * 8;
#pragma unroll
            for (int j = 0; j < 4; j++) {
                float2 f = __half22float2(hp[j]);
                KV[(d + 2 * j) * VPITCH + r]     = f.x;
                KV[(d + 2 * j + 1) * VPITCH + r] = f.y;
            }
        }
        __syncthreads();

#pragma unroll
        for (int ks = 0; ks < 16; ks++) {
            int k0 = ks * 8;
            int keyg = kc * 128 + k0;
            uint32_t pa[4];
            pa[0] = scoresT_u[(keyg + c) * SP + q0 + g];
            pa[1] = scoresT_u[(keyg + c) * SP + q0 + 8 + g];
            pa[2] = scoresT_u[(keyg + c + 4) * SP + q0 + g];
            pa[3] = scoresT_u[(keyg + c + 4) * SP + q0 + 8 + g];
#pragma unroll
            for (int nt = 0; nt < 2; nt++) {
                uint32_t vb[2];
                int dn = d0 + nt * 8 + g;
                vb[0] = KV_u[dn * VPITCH + k0 + c];
                vb[1] = KV_u[dn * VPITCH + k0 + c + 4];
                mma_tf32(accO[nt], pa, vb);
            }
        }
    }

#pragma unroll
    for (int nt = 0; nt < 2; nt++) {
        int dcol = colbase + d0 + nt * 8 + 2 * c;
        __half2* r0 = (__half2*)&O[(size_t)(qbase + q0 + g) * DIM + dcol];
        __half2* r1 = (__half2*)&O[(size_t)(qbase + q0 + 8 + g) * DIM + dcol];
        *r0 = __floats2half2_rn(accO[nt][0], accO[nt][1]);
        *r1 = __floats2half2_rn(accO[nt][2], accO[nt][3]);
    }
}

// ---------------- launch ----------------
extern "C" void kernel_launch(void* const* d_in, const int* in_sizes, int n_in,
                              void* d_out, int out_size) {
    const float* hidden = (const float*)d_in[0];
    const float* Wq = (const float*)d_in[2];
    const float* bq = (const float*)d_in[3];
    const float* Wk = (const float*)d_in[4];
    const float* Wv = (const float*)d_in[5];
    const float* bv = (const float*)d_in[6];
    const float* Wo = (const float*)d_in[7];
    const float* bo = (const float*)d_in[8];
    const float* g1 = (const float*)d_in[9];
    const float* b1 = (const float*)d_in[10];
    const float* Wf1 = (const float*)d_in[11];
    const float* bf1 = (const float*)d_in[12];
    const float* Wf2 = (const float*)d_in[13];
    const float* bf2 = (const float*)d_in[14];
    const float* g2 = (const float*)d_in[15];
    const float* b2 = (const float*)d_in[16];
    float* out = (float*)d_out;

    __half *xln, *qkv, *attnh, *yln, *mid;
    __half *wqkvt, *wot, *wf1t, *wf2t;
    float *h, *bqkv;
    cudaGetSymbolAddress((void**)&xln, g_xln);
    cudaGetSymbolAddress((void**)&qkv, g_qkv);
    cudaGetSymbolAddress((void**)&attnh, g_attnh);
    cudaGetSymbolAddress((void**)&h, g_h);
    cudaGetSymbolAddress((void**)&yln, g_yln);
    cudaGetSymbolAddress((void**)&mid, g_mid);
    cudaGetSymbolAddress((void**)&wqkvt, g_wqkvt);
    cudaGetSymbolAddress((void**)&bqkv, g_bqkv);
    cudaGetSymbolAddress((void**)&wot, g_wot);
    cudaGetSymbolAddress((void**)&wf1t, g_wf1t);
    cudaGetSymbolAddress((void**)&wf2t, g_wf2t);

    const int ATTN_SMEM = ATTN_SMEM_FLOATS * 4;
    cudaFuncSetAttribute(attn_kernel, cudaFuncAttributeMaxDynamicSharedMemorySize, ATTN_SMEM);
    cudaFuncSetAttribute(mma_gemm<EPI_BIAS, 1>, cudaFuncAttributeMaxDynamicSharedMemorySize, GEMM_DSMEM);
    cudaFuncSetAttribute(mma_gemm<EPI_GELU, 1>, cudaFuncAttributeMaxDynamicSharedMemorySize, GEMM_DSMEM);
    cudaFuncSetAttribute(mma_gemm<EPI_BIAS_RES, 0>, cudaFuncAttributeMaxDynamicSharedMemorySize, GEMM_DSMEM);

    dim3 tb(32, 8);
    transpose_k<<<dim3(DIM / 32, DIM / 32), tb>>>(Wq, wqkvt, DIM, DIM, DIM);
    transpose_k<<<dim3(DIM / 32, DIM / 32), tb>>>(Wk, wqkvt + (size_t)DIM * DIM, DIM, DIM, DIM);
    transpose_k<<<dim3(DIM / 32, DIM / 32), tb>>>(Wv, wqkvt + (size_t)2 * DIM * DIM, DIM, DIM, DIM);
    transpose_k<<<dim3(DIM / 32, DIM / 32), tb>>>(Wo, wot, DIM, DIM, DIM);
    transpose_k<<<dim3(FFNDIM / 32, DIM / 32), tb>>>(Wf1, wf1t, DIM, FFNDIM, DIM);
    transpose_k<<<dim3(DIM / 32, FFNDIM / 32), tb>>>(Wf2, wf2t, FFNDIM, DIM, FFNDIM);
    qkvbias_k<<<QKVN / 256, 256>>>(bq, bv, bqkv);

    dim3 gQKV(QKVN / 128, SEQ / 128);
    dim3 gD(DIM / 128, SEQ / 128);
    dim3 gF(FFNDIM / 128, SEQ / 128);

    // LN1 (half out)
    ln_kernel<<<SEQ, 256>>>(hidden, g1, b1, xln);
    // fused QKV GEMM -> half [4096, 3840]
    mma_gemm<EPI_BIAS, 1><<<gQKV, 256, GEMM_DSMEM>>>(xln, wqkvt, bqkv, nullptr, qkv, QKVN, DIM);
    // attention (block-diagonal), half in/out
    attn_kernel<<<dim3(16, NH, 8), 256, ATTN_SMEM>>>(qkv, qkv + DIM, qkv + 2 * DIM, attnh, QKVN);
    // O proj + residual (fp32 out)
    mma_gemm<EPI_BIAS_RES, 0><<<gD, 256, GEMM_DSMEM>>>(attnh, wot, bo, hidden, h, DIM, DIM);
    // LN2 (half out)
    ln_kernel<<<SEQ, 256>>>(h, g2, b2, yln);
    // FFN
    mma_gemm<EPI_GELU, 1><<<gF, 256, GEMM_DSMEM>>>(yln, wf1t, bf1, nullptr, mid, FFNDIM, DIM);
    mma_gemm<EPI_BIAS_RES, 0><<<gD, 256, GEMM_DSMEM>>>(mid, wf2t, bf2, h, out, DIM, FFNDIM);
}

// round 13
// speedup vs baseline: 1.0781x; 1.0781x over previous
#include <cuda_runtime.h>
#include <cuda_fp16.h>
#include <math.h>
#include <stdint.h>

#define SEQ 4096
#define DIM 1280
#define NH 20
#define HD 64
#define FFNDIM 5120
#define SEGLEN 512
#define QKVN 3840

// ---------------- scratch (no allocations allowed) ----------------
__device__ __half g_xln[SEQ * DIM];
__device__ __half g_qkv[(size_t)SEQ * QKVN];
__device__ __half g_attnh[SEQ * DIM];
__device__ float  g_h[SEQ * DIM];
__device__ __half g_yln[SEQ * DIM];
__device__ __half g_mid[(size_t)SEQ * FFNDIM];
__device__ __half g_wqkvt[(size_t)QKVN * DIM];
__device__ float  g_bqkv[QKVN];
__device__ __half g_wot[DIM * DIM];
__device__ __half g_wf1t[(size_t)FFNDIM * DIM];
__device__ __half g_wf2t[(size_t)DIM * FFNDIM];

// ---------------- helpers ----------------
__device__ __forceinline__ float f2tf_f(float x) {
    uint32_t u;
    asm("cvt.rna.tf32.f32 %0, %1;" : "=r"(u) : "f"(x));
    return __uint_as_float(u);
}

__device__ __forceinline__ void mma_f16(float* d, const uint32_t* a,
                                        const uint32_t* b) {
    asm volatile(
        "mma.sync.aligned.m16n8k16.row.col.f32.f16.f16.f32 "
        "{%0,%1,%2,%3}, {%4,%5,%6,%7}, {%8,%9}, {%0,%1,%2,%3};"
        : "+f"(d[0]), "+f"(d[1]), "+f"(d[2]), "+f"(d[3])
        : "r"(a[0]), "r"(a[1]), "r"(a[2]), "r"(a[3]),
          "r"(b[0]), "r"(b[1]));
}

__device__ __forceinline__ void mma_tf32(float* d, const uint32_t* a,
                                         const uint32_t* b) {
    asm volatile(
        "mma.sync.aligned.m16n8k8.row.col.f32.tf32.tf32.f32 "
        "{%0,%1,%2,%3}, {%4,%5,%6,%7}, {%8,%9}, {%0,%1,%2,%3};"
        : "+f"(d[0]), "+f"(d[1]), "+f"(d[2]), "+f"(d[3])
        : "r"(a[0]), "r"(a[1]), "r"(a[2]), "r"(a[3]),
          "r"(b[0]), "r"(b[1]));
}

__device__ __forceinline__ uint32_t smem_u32(const void* p) {
    uint32_t a;
    asm("{ .reg .u64 t; cvta.to.shared.u64 t, %1; cvt.u32.u64 %0, t; }" : "=r"(a) : "l"(p));
    return a;
}
#define CP_ASYNC16(s, g) \
    asm volatile("cp.async.cg.shared.global [%0], [%1], 16;" :: "r"(s), "l"(g))
#define CP_COMMIT() asm volatile("cp.async.commit_group;" ::: "memory")
#define CP_WAIT1() asm volatile("cp.async.wait_group 1;" ::: "memory")

#define LDSM_X4(r0, r1, r2, r3, addr)                                        \
    asm volatile("ldmatrix.sync.aligned.m8n8.x4.shared.b16 {%0,%1,%2,%3}, [%4];" \
        : "=r"(r0), "=r"(r1), "=r"(r2), "=r"(r3) : "r"(addr))
#define LDSM_X2(r0, r1, addr)                                                \
    asm volatile("ldmatrix.sync.aligned.m8n8.x2.shared.b16 {%0,%1}, [%2];"   \
        : "=r"(r0), "=r"(r1) : "r"(addr))

// ---------------- transpose to half ----------------
__global__ void transpose_k(const float* __restrict__ in, __half* __restrict__ out,
                            int R, int C, int ldo) {
    __shared__ float t[32][33];
    int c = blockIdx.x * 32 + threadIdx.x;
    int r = blockIdx.y * 32 + threadIdx.y;
#pragma unroll
    for (int j = 0; j < 32; j += 8)
        t[threadIdx.y + j][threadIdx.x] = in[(size_t)(r + j) * C + c];
    __syncthreads();
    int oc = blockIdx.y * 32 + threadIdx.x;
    int orr = blockIdx.x * 32 + threadIdx.y;
#pragma unroll
    for (int j = 0; j < 32; j += 8)
        out[(size_t)(orr + j) * ldo + oc] = __float2half(t[threadIdx.x][threadIdx.y + j]);
}

// ---------------- fused QKV bias ----------------
__global__ void qkvbias_k(const float* __restrict__ bq, const float* __restrict__ bv,
                          float* __restrict__ out) {
    int i = blockIdx.x * 256 + threadIdx.x;
    float v = 0.f;
    if (i < DIM) v = bq[i];
    else if (i >= 2 * DIM) v = bv[i - 2 * DIM];
    out[i] = v;
}

// ---------------- LayerNorm (half output) ----------------
__global__ void ln_kernel(const float* __restrict__ x, const float* __restrict__ g,
                          const float* __restrict__ b, __half* __restrict__ y) {
    int row = blockIdx.x;
    const float* xr = x + (size_t)row * DIM;
    float v[5];
    float s = 0.f, sq = 0.f;
#pragma unroll
    for (int i = 0; i < 5; i++) {
        v[i] = xr[threadIdx.x + i * 256];
        s += v[i];
        sq += v[i] * v[i];
    }
    __shared__ float red[64];
#pragma unroll
    for (int o = 16; o > 0; o >>= 1) {
        s += __shfl_xor_sync(0xFFFFFFFFu, s, o);
        sq += __shfl_xor_sync(0xFFFFFFFFu, sq, o);
    }
    int w = threadIdx.x >> 5, l = threadIdx.x & 31;
    if (l == 0) { red[w] = s; red[w + 8] = sq; }
    __syncthreads();
    if (threadIdx.x < 32) {
        float ss = (threadIdx.x < 8) ? red[threadIdx.x] : 0.f;
        float qq = (threadIdx.x < 8) ? red[threadIdx.x + 8] : 0.f;
#pragma unroll
        for (int o = 4; o > 0; o >>= 1) {
            ss += __shfl_xor_sync(0xFFFFFFFFu, ss, o);
            qq += __shfl_xor_sync(0xFFFFFFFFu, qq, o);
        }
        if (threadIdx.x == 0) { red[32] = ss; red[33] = qq; }
    }
    __syncthreads();
    float mu  = red[32] * (1.f / DIM);
    float var = red[33] * (1.f / DIM) - mu * mu;
    float inv = rsqrtf(var + 1e-5f);
    __half* yr = y + (size_t)row * DIM;
#pragma unroll
    for (int i = 0; i < 5; i++) {
        int c = threadIdx.x + i * 256;
        yr[c] = __float2half((v[i] - mu) * inv * g[c] + b[c]);
    }
}

// ---------------- fp16 mma GEMM: BK=64, 3-stage cp.async, 1 sync/iter ----------------
#define EPI_NONE 0
#define EPI_BIAS 1
#define EPI_GELU 2
#define EPI_BIAS_RES 3

#define BK 64                           // halves per K chunk
#define PWH 72                          // pitch in halves (144 B/row)
#define ROWB (PWH * 2)                  // 144
#define A_HALVES (128 * PWH)            // 9216 halves
#define A_BYTES (A_HALVES * 2)          // 18432
#define STAGE_BYTES (2 * A_BYTES)       // 36864
#define GEMM_DSMEM (3 * STAGE_BYTES)    // 110592

template <int EPI, int OUTH>
__global__ __launch_bounds__(256, 2) void mma_gemm(
    const __half* __restrict__ A, const __half* __restrict__ Bt,
    const float* __restrict__ bias, const float* __restrict__ res,
    void* __restrict__ Cv, int Ntot, int K) {
    extern __shared__ __align__(16) char smc[];
    uint32_t smb = smem_u32(smc);

    int tid = threadIdx.x;
    int wid = tid >> 5, lane = tid & 31;
    int warp_m = wid & 1;
    int warp_n = wid >> 1;
    int g = lane >> 2, c = lane & 3;
    int br = blockIdx.y * 128, bc = blockIdx.x * 128;

    const __half* Abase = A + (size_t)br * K;
    const __half* Bbase = Bt + (size_t)bc * K;

    const int NIT = K / BK;

    // per-thread ldmatrix base offsets (bytes, within stage)
    uint32_t a_off = (uint32_t)(warp_m * 64 + (lane & 15)) * ROWB + ((lane >> 4) << 4);
    uint32_t b_off = A_BYTES + (uint32_t)(warp_n * 32 + (lane & 7)) * ROWB + (((lane >> 3) & 1) << 4);

    float acc[4][4][4];
#pragma unroll
    for (int i = 0; i < 4; i++)
#pragma unroll
        for (int j = 0; j < 4; j++)
#pragma unroll
            for (int u = 0; u < 4; u++) acc[i][j][u] = 0.f;

    // per stage: A tile 128 rows x 8 chunks of 16B; same for B.
#define ISSUE_STAGE(st)                                                       \
    do {                                                                      \
        int _k0 = (st) * BK;                                                  \
        uint32_t _sa = smb + ((st) % 3) * STAGE_BYTES;                        \
        uint32_t _sb = _sa + A_BYTES;                                         \
        _Pragma("unroll")                                                     \
        for (int _i = 0; _i < 4; _i++) {                                      \
            int _s = tid + _i * 256;                                          \
            int _row = _s >> 3, _f8 = _s & 7;                                 \
            uint32_t _so = (uint32_t)(_row * ROWB + _f8 * 16);                \
            CP_ASYNC16(_sa + _so, Abase + (size_t)_row * K + _k0 + _f8 * 8);  \
            CP_ASYNC16(_sb + _so, Bbase + (size_t)_row * K + _k0 + _f8 * 8);  \
        }                                                                     \
    } while (0)

    ISSUE_STAGE(0);
    CP_COMMIT();
    ISSUE_STAGE(1);
    CP_COMMIT();

    for (int it = 0; it < NIT; it++) {
        CP_WAIT1();
        __syncthreads();
        if (it + 2 < NIT) {
            ISSUE_STAGE(it + 2);
        }
        CP_COMMIT();

        uint32_t sbase = smb + (it % 3) * STAGE_BYTES;
        uint32_t abase = sbase + a_off;
        uint32_t bbase = sbase + b_off;
#pragma unroll
        for (int kk = 0; kk < 4; kk++) {
            uint32_t koff = kk * 32;
            uint32_t af[4][4], bf[4][2];
#pragma unroll
            for (int mt = 0; mt < 4; mt++)
                LDSM_X4(af[mt][0], af[mt][1], af[mt][2], af[mt][3],
                        abase + (uint32_t)mt * 16 * ROWB + koff);
#pragma unroll
            for (int nt = 0; nt < 4; nt++)
                LDSM_X2(bf[nt][0], bf[nt][1],
                        bbase + (uint32_t)nt * 8 * ROWB + koff);
#pragma unroll
            for (int mt = 0; mt < 4; mt++)
#pragma unroll
                for (int nt = 0; nt < 4; nt++)
                    mma_f16(acc[mt][nt], af[mt], bf[nt]);
        }
        // no trailing sync: next iter's top barrier orders stage reuse
    }

    // epilogue
#pragma unroll
    for (int mt = 0; mt < 4; mt++) {
#pragma unroll
        for (int nt = 0; nt < 4; nt++) {
            int col = bc + warp_n * 32 + nt * 8 + c * 2;
#pragma unroll
            for (int half = 0; half < 2; half++) {
                int row = br + warp_m * 64 + mt * 16 + g + half * 8;
                float x0 = acc[mt][nt][half * 2 + 0];
                float x1 = acc[mt][nt][half * 2 + 1];
                if (EPI == EPI_BIAS || EPI == EPI_GELU || EPI == EPI_BIAS_RES) {
                    x0 += bias[col];
                    x1 += bias[col + 1];
                }
                if (EPI == EPI_GELU) {
                    x0 = 0.5f * x0 * (1.f + erff(x0 * 0.70710678118654752f));
                    x1 = 0.5f * x1 * (1.f + erff(x1 * 0.70710678118654752f));
                }
                if (EPI == EPI_BIAS_RES) {
                    float2 r2 = *(const float2*)(res + (size_t)row * Ntot + col);
                    x0 += r2.x;
                    x1 += r2.y;
                }
                if (OUTH) {
                    __half2* Ch = (__half2*)Cv;
                    Ch[((size_t)row * Ntot + col) >> 1] = __floats2half2_rn(x0, x1);
                } else {
                    float* Cf = (float*)Cv;
                    *(float2*)(Cf + (size_t)row * Ntot + col) = make_float2(x0, x1);
                }
            }
        }
    }
}

// ---------------- tensor-core block-diagonal attention (half in/out) ----------------
#define SP 33
#define QPITCH 68
#define VPITCH 132
#define ASM_Q (512 * SP)
#define ASM_KV (ASM_Q + 32 * QPITCH)
#define ATTN_SMEM_FLOATS (ASM_KV + 128 * QPITCH)

__global__ __launch_bounds__(256) void attn_kernel(
    const __half* __restrict__ Q, const __half* __restrict__ Kg,
    const __half* __restrict__ V, __half* __restrict__ O, int ldq) {
    extern __shared__ float sm[];
    float* scoresT = sm;
    float* Qs = sm + ASM_Q;
    float* KV = sm + ASM_KV;
    uint32_t* scoresT_u = (uint32_t*)scoresT;
    const uint32_t* Qs_u = (const uint32_t*)Qs;
    const uint32_t* KV_u = (const uint32_t*)KV;

    int tid = threadIdx.x;
    int wid = tid >> 5, lane = tid & 31;
    int g = lane >> 2, c = lane & 3;
    int qt = blockIdx.x;
    int hh = blockIdx.y;
    int sg = blockIdx.z;
    int qbase = sg * SEGLEN + qt * 32;
    int kbase = sg * SEGLEN;
    int colbase = hh * HD;

    {
        int r = tid >> 3, f8 = tid & 7;
        uint4 raw = *(const uint4*)(Q + (size_t)(qbase + r) * ldq + colbase + f8 * 8);
        const __half2* hp = (const __half2*)&raw;
        float* dst = &Qs[r * QPITCH + f8 * 8];
#pragma unroll
        for (int j = 0; j < 4; j++) {
            float2 f = __half22float2(hp[j]);
            dst[2 * j] = f.x * 0.125f;
            dst[2 * j + 1] = f.y * 0.125f;
        }
    }

    // ---- Phase A: S = Q @ K^T ----
    for (int kc = 0; kc < 4; kc++) {
        __syncthreads();
#pragma unroll
        for (int i = 0; i < 4; i++) {
            int s = tid + i * 256;
            int r = s >> 3, f8 = s & 7;
            uint4 raw = *(const uint4*)(Kg + (size_t)(kbase + kc * 128 + r) * ldq + colbase + f8 * 8);
            const __half2* hp = (const __half2*)&raw;
            float* dst = &KV[r * QPITCH + f8 * 8];
#pragma unroll
            for (int j = 0; j < 4; j++) {
                float2 f = __half22float2(hp[j]);
                dst[2 * j] = f.x;
                dst[2 * j + 1] = f.y;
            }
        }
        __syncthreads();

        float accS[2][2][4];
#pragma unroll
        for (int mt = 0; mt < 2; mt++)
#pragma unroll
            for (int nt = 0; nt < 2; nt++)
#pragma unroll
                for (int u = 0; u < 4; u++) accS[mt][nt][u] = 0.f;

#pragma unroll
        for (int ks = 0; ks < 8; ks++) {
            int k0 = ks * 8;
            uint32_t qa[2][4];
#pragma unroll
            for (int mt = 0; mt < 2; mt++) {
                int rm = mt * 16 + g;
                qa[mt][0] = Qs_u[rm * QPITCH + k0 + c];
                qa[mt][1] = Qs_u[(rm + 8) * QPITCH + k0 + c];
                qa[mt][2] = Qs_u[rm * QPITCH + k0 + c + 4];
                qa[mt][3] = Qs_u[(rm + 8) * QPITCH + k0 + c + 4];
            }
#pragma unroll
            for (int nt = 0; nt < 2; nt++) {
                int rk = wid * 16 + nt * 8 + g;
                uint32_t kb[2];
                kb[0] = KV_u[rk * QPITCH + k0 + c];
                kb[1] = KV_u[rk * QPITCH + k0 + c + 4];
#pragma unroll
                for (int mt = 0; mt < 2; mt++)
                    mma_tf32(accS[mt][nt], qa[mt], kb);
            }
        }
#pragma unroll
        for (int mt = 0; mt < 2; mt++)
#pragma unroll
            for (int nt = 0; nt < 2; nt++) {
                int keyg = kc * 128 + wid * 16 + nt * 8 + 2 * c;
                int q0 = mt * 16 + g;
                scoresT[keyg * SP + q0]           = accS[mt][nt][0];
                scoresT[(keyg + 1) * SP + q0]     = accS[mt][nt][1];
                scoresT[keyg * SP + q0 + 8]       = accS[mt][nt][2];
                scoresT[(keyg + 1) * SP + q0 + 8] = accS[mt][nt][3];
            }
    }
    __syncthreads();

    // ---- softmax ----
    {
        int w = wid, l = lane;
        for (int qi = 0; qi < 4; qi++) {
            int q = w + qi * 8;
            float vals[16];
            float m = -1e30f;
#pragma unroll
            for (int s = 0; s < 16; s++) {
                vals[s] = scoresT[(l + s * 32) * SP + q];
                m = fmaxf(m, vals[s]);
            }
#pragma unroll
            for (int o = 16; o > 0; o >>= 1) m = fmaxf(m, __shfl_xor_sync(0xFFFFFFFFu, m, o));
            float sum = 0.f;
#pragma unroll
            for (int s = 0; s < 16; s++) {
                float e = __expf(vals[s] - m);
                vals[s] = e;
                sum += e;
            }
#pragma unroll
            for (int o = 16; o > 0; o >>= 1) sum += __shfl_xor_sync(0xFFFFFFFFu, sum, o);
            float r = 1.f / sum;
#pragma unroll
            for (int s = 0; s < 16; s++)
                scoresT[(l + s * 32) * SP + q] = f2tf_f(vals[s] * r);
        }
    }

    // ---- Phase C: O = P @ V ----
    int mhalf = wid & 1;
    int dq = wid >> 1;
    int q0 = mhalf * 16, d0 = dq * 16;
    float accO[2][4];
#pragma unroll
    for (int nt = 0; nt < 2; nt++)
#pragma unroll
        for (int u = 0; u < 4; u++) accO[nt][u] = 0.f;

    for (int kc = 0; kc < 4; kc++) {
        __syncthreads();
#pragma unroll
        for (int i = 0; i < 4; i++) {
            int s = tid + i * 256;
            int r = s >> 3, f8 = s & 7;
            uint4 raw = *(const uint4*)(V + (size_t)(kbase + kc * 128 + r) * ldq + colbase + f8 * 8);
            const __half2* hp = (const __half2*)&raw;
            int d = f8 * 8;
#pragma unroll
            for (int j = 0; j < 4; j++) {
                float2 f = __half22float2(hp[j]);
                KV[(d + 2 * j) * VPITCH + r]     = f.x;
                KV[(d + 2 * j + 1) * VPITCH + r] = f.y;
            }
        }
        __syncthreads();

#pragma unroll
        for (int ks = 0; ks < 16; ks++) {
            int k0 = ks * 8;
            int keyg = kc * 128 + k0;
            uint32_t pa[4];
            pa[0] = scoresT_u[(keyg + c) * SP + q0 + g];
            pa[1] = scoresT_u[(keyg + c) * SP + q0 + 8 + g];
            pa[2] = scoresT_u[(keyg + c + 4) * SP + q0 + g];
            pa[3] = scoresT_u[(keyg + c + 4) * SP + q0 + 8 + g];
#pragma unroll
            for (int nt = 0; nt < 2; nt++) {
                uint32_t vb[2];
                int dn = d0 + nt * 8 + g;
                vb[0] = KV_u[dn * VPITCH + k0 + c];
                vb[1] = KV_u[dn * VPITCH + k0 + c + 4];
                mma_tf32(accO[nt], pa, vb);
            }
        }
    }

#pragma unroll
    for (int nt = 0; nt < 2; nt++) {
        int dcol = colbase + d0 + nt * 8 + 2 * c;
        __half2* r0 = (__half2*)&O[(size_t)(qbase + q0 + g) * DIM + dcol];
        __half2* r1 = (__half2*)&O[(size_t)(qbase + q0 + 8 + g) * DIM + dcol];
        *r0 = __floats2half2_rn(accO[nt][0], accO[nt][1]);
        *r1 = __floats2half2_rn(accO[nt][2], accO[nt][3]);
    }
}

// ---------------- launch ----------------
extern "C" void kernel_launch(void* const* d_in, const int* in_sizes, int n_in,
                              void* d_out, int out_size) {
    const float* hidden = (const float*)d_in[0];
    const float* Wq = (const float*)d_in[2];
    const float* bq = (const float*)d_in[3];
    const float* Wk = (const float*)d_in[4];
    const float* Wv = (const float*)d_in[5];
    const float* bv = (const float*)d_in[6];
    const float* Wo = (const float*)d_in[7];
    const float* bo = (const float*)d_in[8];
    const float* g1 = (const float*)d_in[9];
    const float* b1 = (const float*)d_in[10];
    const float* Wf1 = (const float*)d_in[11];
    const float* bf1 = (const float*)d_in[12];
    const float* Wf2 = (const float*)d_in[13];
    const float* bf2 = (const float*)d_in[14];
    const float* g2 = (const float*)d_in[15];
    const float* b2 = (const float*)d_in[16];
    float* out = (float*)d_out;

    __half *xln, *qkv, *attnh, *yln, *mid;
    __half *wqkvt, *wot, *wf1t, *wf2t;
    float *h, *bqkv;
    cudaGetSymbolAddress((void**)&xln, g_xln);
    cudaGetSymbolAddress((void**)&qkv, g_qkv);
    cudaGetSymbolAddress((void**)&attnh, g_attnh);
    cudaGetSymbolAddress((void**)&h, g_h);
    cudaGetSymbolAddress((void**)&yln, g_yln);
    cudaGetSymbolAddress((void**)&mid, g_mid);
    cudaGetSymbolAddress((void**)&wqkvt, g_wqkvt);
    cudaGetSymbolAddress((void**)&bqkv, g_bqkv);
    cudaGetSymbolAddress((void**)&wot, g_wot);
    cudaGetSymbolAddress((void**)&wf1t, g_wf1t);
    cudaGetSymbolAddress((void**)&wf2t, g_wf2t);

    const int ATTN_SMEM = ATTN_SMEM_FLOATS * 4;
    cudaFuncSetAttribute(attn_kernel, cudaFuncAttributeMaxDynamicSharedMemorySize, ATTN_SMEM);
    cudaFuncSetAttribute(mma_gemm<EPI_BIAS, 1>, cudaFuncAttributeMaxDynamicSharedMemorySize, GEMM_DSMEM);
    cudaFuncSetAttribute(mma_gemm<EPI_GELU, 1>, cudaFuncAttributeMaxDynamicSharedMemorySize, GEMM_DSMEM);
    cudaFuncSetAttribute(mma_gemm<EPI_BIAS_RES, 0>, cudaFuncAttributeMaxDynamicSharedMemorySize, GEMM_DSMEM);

    dim3 tb(32, 8);
    transpose_k<<<dim3(DIM / 32, DIM / 32), tb>>>(Wq, wqkvt, DIM, DIM, DIM);
    transpose_k<<<dim3(DIM / 32, DIM / 32), tb>>>(Wk, wqkvt + (size_t)DIM * DIM, DIM, DIM, DIM);
    transpose_k<<<dim3(DIM / 32, DIM / 32), tb>>>(Wv, wqkvt + (size_t)2 * DIM * DIM, DIM, DIM, DIM);
    transpose_k<<<dim3(DIM / 32, DIM / 32), tb>>>(Wo, wot, DIM, DIM, DIM);
    transpose_k<<<dim3(FFNDIM / 32, DIM / 32), tb>>>(Wf1, wf1t, DIM, FFNDIM, DIM);
    transpose_k<<<dim3(DIM / 32, FFNDIM / 32), tb>>>(Wf2, wf2t, FFNDIM, DIM, FFNDIM);
    qkvbias_k<<<QKVN / 256, 256>>>(bq, bv, bqkv);

    dim3 gQKV(QKVN / 128, SEQ / 128);
    dim3 gD(DIM / 128, SEQ / 128);
    dim3 gF(FFNDIM / 128, SEQ / 128);

    // LN1 (half out)
    ln_kernel<<<SEQ, 256>>>(hidden, g1, b1, xln);
    // fused QKV GEMM -> half [4096, 3840]
    mma_gemm<EPI_BIAS, 1><<<gQKV, 256, GEMM_DSMEM>>>(xln, wqkvt, bqkv, nullptr, qkv, QKVN, DIM);
    // attention (block-diagonal), half in/out
    attn_kernel<<<dim3(16, NH, 8), 256, ATTN_SMEM>>>(qkv, qkv + DIM, qkv + 2 * DIM, attnh, QKVN);
    // O proj + residual (fp32 out)
    mma_gemm<EPI_BIAS_RES, 0><<<gD, 256, GEMM_DSMEM>>>(attnh, wot, bo, hidden, h, DIM, DIM);
    // LN2 (half out)
    ln_kernel<<<SEQ, 256>>>(h, g2, b2, yln);
    // FFN
    mma_gemm<EPI_GELU, 1><<<gF, 256, GEMM_DSMEM>>>(yln, wf1t, bf1, nullptr, mid, FFNDIM, DIM);
    mma_gemm<EPI_BIAS_RES, 0><<<gD, 256, GEMM_DSMEM>>>(mid, wf2t, bf2, h, out, DIM, FFNDIM);
}

// round 14
// speedup vs baseline: 1.0803x; 1.0021x over previous
#include <cuda_runtime.h>
#include <cuda_fp16.h>
#include <math.h>
#include <stdint.h>

#define SEQ 4096
#define DIM 1280
#define NH 20
#define HD 64
#define FFNDIM 5120
#define SEGLEN 512
#define QKVN 3840

// ---------------- scratch (no allocations allowed) ----------------
__device__ __half g_xln[SEQ * DIM];
__device__ __half g_qkv[(size_t)SEQ * QKVN];
__device__ __half g_attnh[SEQ * DIM];
__device__ float  g_h[SEQ * DIM];
__device__ __half g_yln[SEQ * DIM];
__device__ __half g_mid[(size_t)SEQ * FFNDIM];
__device__ __half g_wqkvt[(size_t)QKVN * DIM];
__device__ float  g_bqkv[QKVN];
__device__ __half g_wot[DIM * DIM];
__device__ __half g_wf1t[(size_t)FFNDIM * DIM];
__device__ __half g_wf2t[(size_t)DIM * FFNDIM];

// ---------------- helpers ----------------
__device__ __forceinline__ float f2tf_f(float x) {
    uint32_t u;
    asm("cvt.rna.tf32.f32 %0, %1;" : "=r"(u) : "f"(x));
    return __uint_as_float(u);
}

__device__ __forceinline__ void mma_f16(float* d, const uint32_t* a,
                                        const uint32_t* b) {
    asm volatile(
        "mma.sync.aligned.m16n8k16.row.col.f32.f16.f16.f32 "
        "{%0,%1,%2,%3}, {%4,%5,%6,%7}, {%8,%9}, {%0,%1,%2,%3};"
        : "+f"(d[0]), "+f"(d[1]), "+f"(d[2]), "+f"(d[3])
        : "r"(a[0]), "r"(a[1]), "r"(a[2]), "r"(a[3]),
          "r"(b[0]), "r"(b[1]));
}

__device__ __forceinline__ void mma_tf32(float* d, const uint32_t* a,
                                         const uint32_t* b) {
    asm volatile(
        "mma.sync.aligned.m16n8k8.row.col.f32.tf32.tf32.f32 "
        "{%0,%1,%2,%3}, {%4,%5,%6,%7}, {%8,%9}, {%0,%1,%2,%3};"
        : "+f"(d[0]), "+f"(d[1]), "+f"(d[2]), "+f"(d[3])
        : "r"(a[0]), "r"(a[1]), "r"(a[2]), "r"(a[3]),
          "r"(b[0]), "r"(b[1]));
}

__device__ __forceinline__ uint32_t smem_u32(const void* p) {
    uint32_t a;
    asm("{ .reg .u64 t; cvta.to.shared.u64 t, %1; cvt.u32.u64 %0, t; }" : "=r"(a) : "l"(p));
    return a;
}
#define CP_ASYNC16(s, g) \
    asm volatile("cp.async.cg.shared.global [%0], [%1], 16;" :: "r"(s), "l"(g))
#define CP_COMMIT() asm volatile("cp.async.commit_group;" ::: "memory")
#define CP_WAIT1() asm volatile("cp.async.wait_group 1;" ::: "memory")

#define LDSM_X4(r0, r1, r2, r3, addr)                                        \
    asm volatile("ldmatrix.sync.aligned.m8n8.x4.shared.b16 {%0,%1,%2,%3}, [%4];" \
        : "=r"(r0), "=r"(r1), "=r"(r2), "=r"(r3) : "r"(addr))
#define LDSM_X2(r0, r1, addr)                                                \
    asm volatile("ldmatrix.sync.aligned.m8n8.x2.shared.b16 {%0,%1}, [%2];"   \
        : "=r"(r0), "=r"(r1) : "r"(addr))

// ---------------- transpose to half ----------------
__global__ void transpose_k(const float* __restrict__ in, __half* __restrict__ out,
                            int R, int C, int ldo) {
    __shared__ float t[32][33];
    int c = blockIdx.x * 32 + threadIdx.x;
    int r = blockIdx.y * 32 + threadIdx.y;
#pragma unroll
    for (int j = 0; j < 32; j += 8)
        t[threadIdx.y + j][threadIdx.x] = in[(size_t)(r + j) * C + c];
    __syncthreads();
    int oc = blockIdx.y * 32 + threadIdx.x;
    int orr = blockIdx.x * 32 + threadIdx.y;
#pragma unroll
    for (int j = 0; j < 32; j += 8)
        out[(size_t)(orr + j) * ldo + oc] = __float2half(t[threadIdx.x][threadIdx.y + j]);
}

// ---------------- fused QKV bias ----------------
__global__ void qkvbias_k(const float* __restrict__ bq, const float* __restrict__ bv,
                          float* __restrict__ out) {
    int i = blockIdx.x * 256 + threadIdx.x;
    float v = 0.f;
    if (i < DIM) v = bq[i];
    else if (i >= 2 * DIM) v = bv[i - 2 * DIM];
    out[i] = v;
}

// ---------------- LayerNorm (half output) ----------------
__global__ void ln_kernel(const float* __restrict__ x, const float* __restrict__ g,
                          const float* __restrict__ b, __half* __restrict__ y) {
    int row = blockIdx.x;
    const float* xr = x + (size_t)row * DIM;
    float v[5];
    float s = 0.f, sq = 0.f;
#pragma unroll
    for (int i = 0; i < 5; i++) {
        v[i] = xr[threadIdx.x + i * 256];
        s += v[i];
        sq += v[i] * v[i];
    }
    __shared__ float red[64];
#pragma unroll
    for (int o = 16; o > 0; o >>= 1) {
        s += __shfl_xor_sync(0xFFFFFFFFu, s, o);
        sq += __shfl_xor_sync(0xFFFFFFFFu, sq, o);
    }
    int w = threadIdx.x >> 5, l = threadIdx.x & 31;
    if (l == 0) { red[w] = s; red[w + 8] = sq; }
    __syncthreads();
    if (threadIdx.x < 32) {
        float ss = (threadIdx.x < 8) ? red[threadIdx.x] : 0.f;
        float qq = (threadIdx.x < 8) ? red[threadIdx.x + 8] : 0.f;
#pragma unroll
        for (int o = 4; o > 0; o >>= 1) {
            ss += __shfl_xor_sync(0xFFFFFFFFu, ss, o);
            qq += __shfl_xor_sync(0xFFFFFFFFu, qq, o);
        }
        if (threadIdx.x == 0) { red[32] = ss; red[33] = qq; }
    }
    __syncthreads();
    float mu  = red[32] * (1.f / DIM);
    float var = red[33] * (1.f / DIM) - mu * mu;
    float inv = rsqrtf(var + 1e-5f);
    __half* yr = y + (size_t)row * DIM;
#pragma unroll
    for (int i = 0; i < 5; i++) {
        int c = threadIdx.x + i * 256;
        yr[c] = __float2half((v[i] - mu) * inv * g[c] + b[c]);
    }
}

// ---------------- fp16 mma GEMM: BK=64, 3-stage cp.async, 1 sync/iter ----------------
#define EPI_NONE 0
#define EPI_BIAS 1
#define EPI_GELU 2
#define EPI_BIAS_RES 3

#define BK 64                           // halves per K chunk
#define PWH 72                          // pitch in halves (144 B/row)
#define ROWB (PWH * 2)                  // 144
#define A_HALVES (128 * PWH)            // 9216 halves
#define A_BYTES (A_HALVES * 2)          // 18432
#define STAGE_BYTES (2 * A_BYTES)       // 36864
#define GEMM_DSMEM (3 * STAGE_BYTES)    // 110592

template <int EPI, int OUTH>
__global__ __launch_bounds__(256, 2) void mma_gemm(
    const __half* __restrict__ A, const __half* __restrict__ Bt,
    const float* __restrict__ bias, const float* __restrict__ res,
    void* __restrict__ Cv, int Ntot, int K) {
    extern __shared__ __align__(16) char smc[];
    uint32_t smb = smem_u32(smc);

    int tid = threadIdx.x;
    int wid = tid >> 5, lane = tid & 31;
    int warp_m = wid & 1;
    int warp_n = wid >> 1;
    int g = lane >> 2, c = lane & 3;
    int br = blockIdx.y * 128, bc = blockIdx.x * 128;

    const __half* Abase = A + (size_t)br * K;
    const __half* Bbase = Bt + (size_t)bc * K;

    const int NIT = K / BK;

    // per-thread ldmatrix base offsets (bytes, within stage)
    uint32_t a_off = (uint32_t)(warp_m * 64 + (lane & 15)) * ROWB + ((lane >> 4) << 4);
    uint32_t b_off = A_BYTES + (uint32_t)(warp_n * 32 + (lane & 7)) * ROWB + (((lane >> 3) & 1) << 4);

    float acc[4][4][4];
#pragma unroll
    for (int i = 0; i < 4; i++)
#pragma unroll
        for (int j = 0; j < 4; j++)
#pragma unroll
            for (int u = 0; u < 4; u++) acc[i][j][u] = 0.f;

    // per stage: A tile 128 rows x 8 chunks of 16B; same for B.
#define ISSUE_STAGE(st)                                                       \
    do {                                                                      \
        int _k0 = (st) * BK;                                                  \
        uint32_t _sa = smb + ((st) % 3) * STAGE_BYTES;                        \
        uint32_t _sb = _sa + A_BYTES;                                         \
        _Pragma("unroll")                                                     \
        for (int _i = 0; _i < 4; _i++) {                                      \
            int _s = tid + _i * 256;                                          \
            int _row = _s >> 3, _f8 = _s & 7;                                 \
            uint32_t _so = (uint32_t)(_row * ROWB + _f8 * 16);                \
            CP_ASYNC16(_sa + _so, Abase + (size_t)_row * K + _k0 + _f8 * 8);  \
            CP_ASYNC16(_sb + _so, Bbase + (size_t)_row * K + _k0 + _f8 * 8);  \
        }                                                                     \
    } while (0)

    ISSUE_STAGE(0);
    CP_COMMIT();
    ISSUE_STAGE(1);
    CP_COMMIT();

    for (int it = 0; it < NIT; it++) {
        CP_WAIT1();
        __syncthreads();
        if (it + 2 < NIT) {
            ISSUE_STAGE(it + 2);
        }
        CP_COMMIT();

        uint32_t sbase = smb + (it % 3) * STAGE_BYTES;
        uint32_t abase = sbase + a_off;
        uint32_t bbase = sbase + b_off;
#pragma unroll
        for (int kk = 0; kk < 4; kk++) {
            uint32_t koff = kk * 32;
            uint32_t af[4][4], bf[4][2];
#pragma unroll
            for (int mt = 0; mt < 4; mt++)
                LDSM_X4(af[mt][0], af[mt][1], af[mt][2], af[mt][3],
                        abase + (uint32_t)mt * 16 * ROWB + koff);
#pragma unroll
            for (int nt = 0; nt < 4; nt++)
                LDSM_X2(bf[nt][0], bf[nt][1],
                        bbase + (uint32_t)nt * 8 * ROWB + koff);
#pragma unroll
            for (int mt = 0; mt < 4; mt++)
#pragma unroll
                for (int nt = 0; nt < 4; nt++)
                    mma_f16(acc[mt][nt], af[mt], bf[nt]);
        }
        // no trailing sync: next iter's top barrier orders stage reuse
    }

    // epilogue
#pragma unroll
    for (int mt = 0; mt < 4; mt++) {
#pragma unroll
        for (int nt = 0; nt < 4; nt++) {
            int col = bc + warp_n * 32 + nt * 8 + c * 2;
#pragma unroll
            for (int half = 0; half < 2; half++) {
                int row = br + warp_m * 64 + mt * 16 + g + half * 8;
                float x0 = acc[mt][nt][half * 2 + 0];
                float x1 = acc[mt][nt][half * 2 + 1];
                if (EPI == EPI_BIAS || EPI == EPI_GELU || EPI == EPI_BIAS_RES) {
                    x0 += bias[col];
                    x1 += bias[col + 1];
                }
                if (EPI == EPI_GELU) {
                    x0 = 0.5f * x0 * (1.f + erff(x0 * 0.70710678118654752f));
                    x1 = 0.5f * x1 * (1.f + erff(x1 * 0.70710678118654752f));
                }
                if (EPI == EPI_BIAS_RES) {
                    float2 r2 = *(const float2*)(res + (size_t)row * Ntot + col);
                    x0 += r2.x;
                    x1 += r2.y;
                }
                if (OUTH) {
                    __half2* Ch = (__half2*)Cv;
                    Ch[((size_t)row * Ntot + col) >> 1] = __floats2half2_rn(x0, x1);
                } else {
                    float* Cf = (float*)Cv;
                    *(float2*)(Cf + (size_t)row * Ntot + col) = make_float2(x0, x1);
                }
            }
        }
    }
}

// ---------------- tensor-core block-diagonal attention (half in/out) ----------------
#define SP 33
#define QPITCH 68
#define VPITCH 132
#define ASM_Q (512 * SP)
#define ASM_KV (ASM_Q + 32 * QPITCH)
#define ATTN_SMEM_FLOATS (ASM_KV + 128 * QPITCH)

__global__ __launch_bounds__(256) void attn_kernel(
    const __half* __restrict__ Q, const __half* __restrict__ Kg,
    const __half* __restrict__ V, __half* __restrict__ O, int ldq) {
    extern __shared__ float sm[];
    float* scoresT = sm;
    float* Qs = sm + ASM_Q;
    float* KV = sm + ASM_KV;
    uint32_t* scoresT_u = (uint32_t*)scoresT;
    const uint32_t* Qs_u = (const uint32_t*)Qs;
    const uint32_t* KV_u = (const uint32_t*)KV;

    int tid = threadIdx.x;
    int wid = tid >> 5, lane = tid & 31;
    int g = lane >> 2, c = lane & 3;
    int qt = blockIdx.x;
    int hh = blockIdx.y;
    int sg = blockIdx.z;
    int qbase = sg * SEGLEN + qt * 32;
    int kbase = sg * SEGLEN;
    int colbase = hh * HD;

    {
        int r = tid >> 3, f8 = tid & 7;
        uint4 raw = *(const uint4*)(Q + (size_t)(qbase + r) * ldq + colbase + f8 * 8);
        const __half2* hp = (const __half2*)&raw;
        float* dst = &Qs[r * QPITCH + f8 * 8];
#pragma unroll
        for (int j = 0; j < 4; j++) {
            float2 f = __half22float2(hp[j]);
            dst[2 * j] = f.x * 0.125f;
            dst[2 * j + 1] = f.y * 0.125f;
        }
    }

    // ---- Phase A: S = Q @ K^T ----
    for (int kc = 0; kc < 4; kc++) {
        __syncthreads();
#pragma unroll
        for (int i = 0; i < 4; i++) {
            int s = tid + i * 256;
            int r = s >> 3, f8 = s & 7;
            uint4 raw = *(const uint4*)(Kg + (size_t)(kbase + kc * 128 + r) * ldq + colbase + f8 * 8);
            const __half2* hp = (const __half2*)&raw;
            float* dst = &KV[r * QPITCH + f8 * 8];
#pragma unroll
            for (int j = 0; j < 4; j++) {
                float2 f = __half22float2(hp[j]);
                dst[2 * j] = f.x;
                dst[2 * j + 1] = f.y;
            }
        }
        __syncthreads();

        float accS[2][2][4];
#pragma unroll
        for (int mt = 0; mt < 2; mt++)
#pragma unroll
            for (int nt = 0; nt < 2; nt++)
#pragma unroll
                for (int u = 0; u < 4; u++) accS[mt][nt][u] = 0.f;

#pragma unroll
        for (int ks = 0; ks < 8; ks++) {
            int k0 = ks * 8;
            uint32_t qa[2][4];
#pragma unroll
            for (int mt = 0; mt < 2; mt++) {
                int rm = mt * 16 + g;
                qa[mt][0] = Qs_u[rm * QPITCH + k0 + c];
                qa[mt][1] = Qs_u[(rm + 8) * QPITCH + k0 + c];
                qa[mt][2] = Qs_u[rm * QPITCH + k0 + c + 4];
                qa[mt][3] = Qs_u[(rm + 8) * QPITCH + k0 + c + 4];
            }
#pragma unroll
            for (int nt = 0; nt < 2; nt++) {
                int rk = wid * 16 + nt * 8 + g;
                uint32_t kb[2];
                kb[0] = KV_u[rk * QPITCH + k0 + c];
                kb[1] = KV_u[rk * QPITCH + k0 + c + 4];
#pragma unroll
                for (int mt = 0; mt < 2; mt++)
                    mma_tf32(accS[mt][nt], qa[mt], kb);
            }
        }
#pragma unroll
        for (int mt = 0; mt < 2; mt++)
#pragma unroll
            for (int nt = 0; nt < 2; nt++) {
                int keyg = kc * 128 + wid * 16 + nt * 8 + 2 * c;
                int q0 = mt * 16 + g;
                scoresT[keyg * SP + q0]           = accS[mt][nt][0];
                scoresT[(keyg + 1) * SP + q0]     = accS[mt][nt][1];
                scoresT[keyg * SP + q0 + 8]       = accS[mt][nt][2];
                scoresT[(keyg + 1) * SP + q0 + 8] = accS[mt][nt][3];
            }
    }
    __syncthreads();

    // ---- softmax ----
    {
        int w = wid, l = lane;
        for (int qi = 0; qi < 4; qi++) {
            int q = w + qi * 8;
            float vals[16];
            float m = -1e30f;
#pragma unroll
            for (int s = 0; s < 16; s++) {
                vals[s] = scoresT[(l + s * 32) * SP + q];
                m = fmaxf(m, vals[s]);
            }
#pragma unroll
            for (int o = 16; o > 0; o >>= 1) m = fmaxf(m, __shfl_xor_sync(0xFFFFFFFFu, m, o));
            float sum = 0.f;
#pragma unroll
            for (int s = 0; s < 16; s++) {
                float e = __expf(vals[s] - m);
                vals[s] = e;
                sum += e;
            }
#pragma unroll
            for (int o = 16; o > 0; o >>= 1) sum += __shfl_xor_sync(0xFFFFFFFFu, sum, o);
            float r = 1.f / sum;
#pragma unroll
            for (int s = 0; s < 16; s++)
                scoresT[(l + s * 32) * SP + q] = f2tf_f(vals[s] * r);
        }
    }

    // ---- Phase C: O = P @ V ----
    int mhalf = wid & 1;
    int dq = wid >> 1;
    int q0 = mhalf * 16, d0 = dq * 16;
    float accO[2][4];
#pragma unroll
    for (int nt = 0; nt < 2; nt++)
#pragma unroll
        for (int u = 0; u < 4; u++) accO[nt][u] = 0.f;

    for (int kc = 0; kc < 4; kc++) {
        __syncthreads();
#pragma unroll
        for (int i = 0; i < 4; i++) {
            int s = tid + i * 256;
            int r = s >> 3, f8 = s & 7;
            uint4 raw = *(const uint4*)(V + (size_t)(kbase + kc * 128 + r) * ldq + colbase + f8 * 8);
            const __half2* hp = (const __half2*)&raw;
            int d = f8 * 8;
#pragma unroll
            for (int j = 0; j < 4; j++) {
                float2 f = __half22float2(hp[j]);
                KV[(d + 2 * j) * VPITCH + r]     = f.x;
                KV[(d + 2 * j + 1) * VPITCH + r] = f.y;
            }
        }
        __syncthreads();

#pragma unroll
        for (int ks = 0; ks < 16; ks++) {
            int k0 = ks * 8;
            int keyg = kc * 128 + k0;
            uint32_t pa[4];
            pa[0] = scoresT_u[(keyg + c) * SP + q0 + g];
            pa[1] = scoresT_u[(keyg + c) * SP + q0 + 8 + g];
            pa[2] = scoresT_u[(keyg + c + 4) * SP + q0 + g];
            pa[3] = scoresT_u[(keyg + c + 4) * SP + q0 + 8 + g];
#pragma unroll
            for (int nt = 0; nt < 2; nt++) {
                uint32_t vb[2];
                int dn = d0 + nt * 8 + g;
                vb[0] = KV_u[dn * VPITCH + k0 + c];
                vb[1] = KV_u[dn * VPITCH + k0 + c + 4];
                mma_tf32(accO[nt], pa, vb);
            }
        }
    }

#pragma unroll
    for (int nt = 0; nt < 2; nt++) {
        int dcol = colbase + d0 + nt * 8 + 2 * c;
        __half2* r0 = (__half2*)&O[(size_t)(qbase + q0 + g) * DIM + dcol];
        __half2* r1 = (__half2*)&O[(size_t)(qbase + q0 + 8 + g) * DIM + dcol];
        *r0 = __floats2half2_rn(accO[nt][0], accO[nt][1]);
        *r1 = __floats2half2_rn(accO[nt][2], accO[nt][3]);
    }
}

// ---------------- launch ----------------
extern "C" void kernel_launch(void* const* d_in, const int* in_sizes, int n_in,
                              void* d_out, int out_size) {
    const float* hidden = (const float*)d_in[0];
    const float* Wq = (const float*)d_in[2];
    const float* bq = (const float*)d_in[3];
    const float* Wk = (const float*)d_in[4];
    const float* Wv = (const float*)d_in[5];
    const float* bv = (const float*)d_in[6];
    const float* Wo = (const float*)d_in[7];
    const float* bo = (const float*)d_in[8];
    const float* g1 = (const float*)d_in[9];
    const float* b1 = (const float*)d_in[10];
    const float* Wf1 = (const float*)d_in[11];
    const float* bf1 = (const float*)d_in[12];
    const float* Wf2 = (const float*)d_in[13];
    const float* bf2 = (const float*)d_in[14];
    const float* g2 = (const float*)d_in[15];
    const float* b2 = (const float*)d_in[16];
    float* out = (float*)d_out;

    __half *xln, *qkv, *attnh, *yln, *mid;
    __half *wqkvt, *wot, *wf1t, *wf2t;
    float *h, *bqkv;
    cudaGetSymbolAddress((void**)&xln, g_xln);
    cudaGetSymbolAddress((void**)&qkv, g_qkv);
    cudaGetSymbolAddress((void**)&attnh, g_attnh);
    cudaGetSymbolAddress((void**)&h, g_h);
    cudaGetSymbolAddress((void**)&yln, g_yln);
    cudaGetSymbolAddress((void**)&mid, g_mid);
    cudaGetSymbolAddress((void**)&wqkvt, g_wqkvt);
    cudaGetSymbolAddress((void**)&bqkv, g_bqkv);
    cudaGetSymbolAddress((void**)&wot, g_wot);
    cudaGetSymbolAddress((void**)&wf1t, g_wf1t);
    cudaGetSymbolAddress((void**)&wf2t, g_wf2t);

    const int ATTN_SMEM = ATTN_SMEM_FLOATS * 4;
    cudaFuncSetAttribute(attn_kernel, cudaFuncAttributeMaxDynamicSharedMemorySize, ATTN_SMEM);
    cudaFuncSetAttribute(mma_gemm<EPI_BIAS, 1>, cudaFuncAttributeMaxDynamicSharedMemorySize, GEMM_DSMEM);
    cudaFuncSetAttribute(mma_gemm<EPI_GELU, 1>, cudaFuncAttributeMaxDynamicSharedMemorySize, GEMM_DSMEM);
    cudaFuncSetAttribute(mma_gemm<EPI_BIAS_RES, 0>, cudaFuncAttributeMaxDynamicSharedMemorySize, GEMM_DSMEM);

    dim3 tb(32, 8);
    transpose_k<<<dim3(DIM / 32, DIM / 32), tb>>>(Wq, wqkvt, DIM, DIM, DIM);
    transpose_k<<<dim3(DIM / 32, DIM / 32), tb>>>(Wk, wqkvt + (size_t)DIM * DIM, DIM, DIM, DIM);
    transpose_k<<<dim3(DIM / 32, DIM / 32), tb>>>(Wv, wqkvt + (size_t)2 * DIM * DIM, DIM, DIM, DIM);
    transpose_k<<<dim3(DIM / 32, DIM / 32), tb>>>(Wo, wot, DIM, DIM, DIM);
    transpose_k<<<dim3(FFNDIM / 32, DIM / 32), tb>>>(Wf1, wf1t, DIM, FFNDIM, DIM);
    transpose_k<<<dim3(DIM / 32, FFNDIM / 32), tb>>>(Wf2, wf2t, FFNDIM, DIM, FFNDIM);
    qkvbias_k<<<QKVN / 256, 256>>>(bq, bv, bqkv);

    dim3 gQKV(QKVN / 128, SEQ / 128);
    dim3 gD(DIM / 128, SEQ / 128);
    dim3 gF(FFNDIM / 128, SEQ / 128);

    // LN1 (half out)
    ln_kernel<<<SEQ, 256>>>(hidden, g1, b1, xln);
    // fused QKV GEMM -> half [4096, 3840]
    mma_gemm<EPI_BIAS, 1><<<gQKV, 256, GEMM_DSMEM>>>(xln, wqkvt, bqkv, nullptr, qkv, QKVN, DIM);
    // attention (block-diagonal), half in/out
    attn_kernel<<<dim3(16, NH, 8), 256, ATTN_SMEM>>>(qkv, qkv + DIM, qkv + 2 * DIM, attnh, QKVN);
    // O proj + residual (fp32 out)
    mma_gemm<EPI_BIAS_RES, 0><<<gD, 256, GEMM_DSMEM>>>(attnh, wot, bo, hidden, h, DIM, DIM);
    // LN2 (half out)
    ln_kernel<<<SEQ, 256>>>(h, g2, b2, yln);
    // FFN
    mma_gemm<EPI_GELU, 1><<<gF, 256, GEMM_DSMEM>>>(yln, wf1t, bf1, nullptr, mid, FFNDIM, DIM);
    mma_gemm<EPI_BIAS_RES, 0><<<gD, 256, GEMM_DSMEM>>>(mid, wf2t, bf2, h, out, DIM, FFNDIM);
}

// round 15
// speedup vs baseline: 1.0804x; 1.0000x over previous
#include <cuda_runtime.h>
#include <cuda_fp16.h>
#include <math.h>
#include <stdint.h>

#define SEQ 4096
#define DIM 1280
#define NH 20
#define HD 64
#define FFNDIM 5120
#define SEGLEN 512
#define QKVN 3840

// ---------------- scratch (no allocations allowed) ----------------
__device__ __half g_xln[SEQ * DIM];
__device__ __half g_qkv[(size_t)SEQ * QKVN];
__device__ __half g_attnh[SEQ * DIM];
__device__ float  g_h[SEQ * DIM];
__device__ __half g_yln[SEQ * DIM];
__device__ __half g_mid[(size_t)SEQ * FFNDIM];
__device__ __half g_wqkvt[(size_t)QKVN * DIM];
__device__ float  g_bqkv[QKVN];
__device__ __half g_wot[DIM * DIM];
__device__ __half g_wf1t[(size_t)FFNDIM * DIM];
__device__ __half g_wf2t[(size_t)DIM * FFNDIM];

// ---------------- helpers ----------------
__device__ __forceinline__ float f2tf_f(float x) {
    uint32_t u;
    asm("cvt.rna.tf32.f32 %0, %1;" : "=r"(u) : "f"(x));
    return __uint_as_float(u);
}

__device__ __forceinline__ void mma_f16(float* d, const uint32_t* a,
                                        const uint32_t* b) {
    asm volatile(
        "mma.sync.aligned.m16n8k16.row.col.f32.f16.f16.f32 "
        "{%0,%1,%2,%3}, {%4,%5,%6,%7}, {%8,%9}, {%0,%1,%2,%3};"
        : "+f"(d[0]), "+f"(d[1]), "+f"(d[2]), "+f"(d[3])
        : "r"(a[0]), "r"(a[1]), "r"(a[2]), "r"(a[3]),
          "r"(b[0]), "r"(b[1]));
}

__device__ __forceinline__ void mma_tf32(float* d, const uint32_t* a,
                                         const uint32_t* b) {
    asm volatile(
        "mma.sync.aligned.m16n8k8.row.col.f32.tf32.tf32.f32 "
        "{%0,%1,%2,%3}, {%4,%5,%6,%7}, {%8,%9}, {%0,%1,%2,%3};"
        : "+f"(d[0]), "+f"(d[1]), "+f"(d[2]), "+f"(d[3])
        : "r"(a[0]), "r"(a[1]), "r"(a[2]), "r"(a[3]),
          "r"(b[0]), "r"(b[1]));
}

__device__ __forceinline__ uint32_t smem_u32(const void* p) {
    uint32_t a;
    asm("{ .reg .u64 t; cvta.to.shared.u64 t, %1; cvt.u32.u64 %0, t; }" : "=r"(a) : "l"(p));
    return a;
}
#define CP_ASYNC16(s, g) \
    asm volatile("cp.async.cg.shared.global [%0], [%1], 16;" :: "r"(s), "l"(g))
#define CP_COMMIT() asm volatile("cp.async.commit_group;" ::: "memory")
#define CP_WAIT1() asm volatile("cp.async.wait_group 1;" ::: "memory")

#define LDSM_X4(r0, r1, r2, r3, addr)                                        \
    asm volatile("ldmatrix.sync.aligned.m8n8.x4.shared.b16 {%0,%1,%2,%3}, [%4];" \
        : "=r"(r0), "=r"(r1), "=r"(r2), "=r"(r3) : "r"(addr))
#define LDSM_X2(r0, r1, addr)                                                \
    asm volatile("ldmatrix.sync.aligned.m8n8.x2.shared.b16 {%0,%1}, [%2];"   \
        : "=r"(r0), "=r"(r1) : "r"(addr))

// ---------------- transpose to half ----------------
__global__ void transpose_k(const float* __restrict__ in, __half* __restrict__ out,
                            int R, int C, int ldo) {
    __shared__ float t[32][33];
    int c = blockIdx.x * 32 + threadIdx.x;
    int r = blockIdx.y * 32 + threadIdx.y;
#pragma unroll
    for (int j = 0; j < 32; j += 8)
        t[threadIdx.y + j][threadIdx.x] = in[(size_t)(r + j) * C + c];
    __syncthreads();
    int oc = blockIdx.y * 32 + threadIdx.x;
    int orr = blockIdx.x * 32 + threadIdx.y;
#pragma unroll
    for (int j = 0; j < 32; j += 8)
        out[(size_t)(orr + j) * ldo + oc] = __float2half(t[threadIdx.x][threadIdx.y + j]);
}

// ---------------- fused QKV bias ----------------
__global__ void qkvbias_k(const float* __restrict__ bq, const float* __restrict__ bv,
                          float* __restrict__ out) {
    int i = blockIdx.x * 256 + threadIdx.x;
    float v = 0.f;
    if (i < DIM) v = bq[i];
    else if (i >= 2 * DIM) v = bv[i - 2 * DIM];
    out[i] = v;
}

// ---------------- LayerNorm (half output) ----------------
__global__ void ln_kernel(const float* __restrict__ x, const float* __restrict__ g,
                          const float* __restrict__ b, __half* __restrict__ y) {
    int row = blockIdx.x;
    const float* xr = x + (size_t)row * DIM;
    float v[5];
    float s = 0.f, sq = 0.f;
#pragma unroll
    for (int i = 0; i < 5; i++) {
        v[i] = xr[threadIdx.x + i * 256];
        s += v[i];
        sq += v[i] * v[i];
    }
    __shared__ float red[64];
#pragma unroll
    for (int o = 16; o > 0; o >>= 1) {
        s += __shfl_xor_sync(0xFFFFFFFFu, s, o);
        sq += __shfl_xor_sync(0xFFFFFFFFu, sq, o);
    }
    int w = threadIdx.x >> 5, l = threadIdx.x & 31;
    if (l == 0) { red[w] = s; red[w + 8] = sq; }
    __syncthreads();
    if (threadIdx.x < 32) {
        float ss = (threadIdx.x < 8) ? red[threadIdx.x] : 0.f;
        float qq = (threadIdx.x < 8) ? red[threadIdx.x + 8] : 0.f;
#pragma unroll
        for (int o = 4; o > 0; o >>= 1) {
            ss += __shfl_xor_sync(0xFFFFFFFFu, ss, o);
            qq += __shfl_xor_sync(0xFFFFFFFFu, qq, o);
        }
        if (threadIdx.x == 0) { red[32] = ss; red[33] = qq; }
    }
    __syncthreads();
    float mu  = red[32] * (1.f / DIM);
    float var = red[33] * (1.f / DIM) - mu * mu;
    float inv = rsqrtf(var + 1e-5f);
    __half* yr = y + (size_t)row * DIM;
#pragma unroll
    for (int i = 0; i < 5; i++) {
        int c = threadIdx.x + i * 256;
        yr[c] = __float2half((v[i] - mu) * inv * g[c] + b[c]);
    }
}

// ---------------- fp16 mma GEMM: BK=64, 3-stage cp.async, 1 sync/iter ----------------
#define EPI_NONE 0
#define EPI_BIAS 1
#define EPI_GELU 2
#define EPI_BIAS_RES 3

#define BK 64                           // halves per K chunk
#define PWH 72                          // pitch in halves (144 B/row)
#define ROWB (PWH * 2)                  // 144
#define A_HALVES (128 * PWH)            // 9216 halves
#define A_BYTES (A_HALVES * 2)          // 18432
#define STAGE_BYTES (2 * A_BYTES)       // 36864
#define GEMM_DSMEM (3 * STAGE_BYTES)    // 110592

template <int EPI, int OUTH>
__global__ __launch_bounds__(256, 2) void mma_gemm(
    const __half* __restrict__ A, const __half* __restrict__ Bt,
    const float* __restrict__ bias, const float* __restrict__ res,
    void* __restrict__ Cv, int Ntot, int K) {
    extern __shared__ __align__(16) char smc[];
    uint32_t smb = smem_u32(smc);

    int tid = threadIdx.x;
    int wid = tid >> 5, lane = tid & 31;
    int warp_m = wid & 1;
    int warp_n = wid >> 1;
    int g = lane >> 2, c = lane & 3;
    int br = blockIdx.y * 128, bc = blockIdx.x * 128;

    const __half* Abase = A + (size_t)br * K;
    const __half* Bbase = Bt + (size_t)bc * K;

    const int NIT = K / BK;

    // per-thread ldmatrix base offsets (bytes, within stage)
    uint32_t a_off = (uint32_t)(warp_m * 64 + (lane & 15)) * ROWB + ((lane >> 4) << 4);
    uint32_t b_off = A_BYTES + (uint32_t)(warp_n * 32 + (lane & 7)) * ROWB + (((lane >> 3) & 1) << 4);

    float acc[4][4][4];
#pragma unroll
    for (int i = 0; i < 4; i++)
#pragma unroll
        for (int j = 0; j < 4; j++)
#pragma unroll
            for (int u = 0; u < 4; u++) acc[i][j][u] = 0.f;

    // per stage: A tile 128 rows x 8 chunks of 16B; same for B.
#define ISSUE_STAGE(st)                                                       \
    do {                                                                      \
        int _k0 = (st) * BK;                                                  \
        uint32_t _sa = smb + ((st) % 3) * STAGE_BYTES;                        \
        uint32_t _sb = _sa + A_BYTES;                                         \
        _Pragma("unroll")                                                     \
        for (int _i = 0; _i < 4; _i++) {                                      \
            int _s = tid + _i * 256;                                          \
            int _row = _s >> 3, _f8 = _s & 7;                                 \
            uint32_t _so = (uint32_t)(_row * ROWB + _f8 * 16);                \
            CP_ASYNC16(_sa + _so, Abase + (size_t)_row * K + _k0 + _f8 * 8);  \
            CP_ASYNC16(_sb + _so, Bbase + (size_t)_row * K + _k0 + _f8 * 8);  \
        }                                                                     \
    } while (0)

    ISSUE_STAGE(0);
    CP_COMMIT();
    ISSUE_STAGE(1);
    CP_COMMIT();

    for (int it = 0; it < NIT; it++) {
        CP_WAIT1();
        __syncthreads();
        if (it + 2 < NIT) {
            ISSUE_STAGE(it + 2);
        }
        CP_COMMIT();

        uint32_t sbase = smb + (it % 3) * STAGE_BYTES;
        uint32_t abase = sbase + a_off;
        uint32_t bbase = sbase + b_off;
#pragma unroll
        for (int kk = 0; kk < 4; kk++) {
            uint32_t koff = kk * 32;
            uint32_t af[4][4], bf[4][2];
#pragma unroll
            for (int mt = 0; mt < 4; mt++)
                LDSM_X4(af[mt][0], af[mt][1], af[mt][2], af[mt][3],
                        abase + (uint32_t)mt * 16 * ROWB + koff);
#pragma unroll
            for (int nt = 0; nt < 4; nt++)
                LDSM_X2(bf[nt][0], bf[nt][1],
                        bbase + (uint32_t)nt * 8 * ROWB + koff);
#pragma unroll
            for (int mt = 0; mt < 4; mt++)
#pragma unroll
                for (int nt = 0; nt < 4; nt++)
                    mma_f16(acc[mt][nt], af[mt], bf[nt]);
        }
        // no trailing sync: next iter's top barrier orders stage reuse
    }

    // epilogue
#pragma unroll
    for (int mt = 0; mt < 4; mt++) {
#pragma unroll
        for (int nt = 0; nt < 4; nt++) {
            int col = bc + warp_n * 32 + nt * 8 + c * 2;
#pragma unroll
            for (int half = 0; half < 2; half++) {
                int row = br + warp_m * 64 + mt * 16 + g + half * 8;
                float x0 = acc[mt][nt][half * 2 + 0];
                float x1 = acc[mt][nt][half * 2 + 1];
                if (EPI == EPI_BIAS || EPI == EPI_GELU || EPI == EPI_BIAS_RES) {
                    x0 += bias[col];
                    x1 += bias[col + 1];
                }
                if (EPI == EPI_GELU) {
                    x0 = 0.5f * x0 * (1.f + erff(x0 * 0.70710678118654752f));
                    x1 = 0.5f * x1 * (1.f + erff(x1 * 0.70710678118654752f));
                }
                if (EPI == EPI_BIAS_RES) {
                    float2 r2 = *(const float2*)(res + (size_t)row * Ntot + col);
                    x0 += r2.x;
                    x1 += r2.y;
                }
                if (OUTH) {
                    __half2* Ch = (__half2*)Cv;
                    Ch[((size_t)row * Ntot + col) >> 1] = __floats2half2_rn(x0, x1);
                } else {
                    float* Cf = (float*)Cv;
                    *(float2*)(Cf + (size_t)row * Ntot + col) = make_float2(x0, x1);
                }
            }
        }
    }
}

// ---------------- tensor-core block-diagonal attention (half in/out) ----------------
#define SP 33
#define QPITCH 68
#define VPITCH 132
#define ASM_Q (512 * SP)
#define ASM_KV (ASM_Q + 32 * QPITCH)
#define ATTN_SMEM_FLOATS (ASM_KV + 128 * QPITCH)

__global__ __launch_bounds__(256) void attn_kernel(
    const __half* __restrict__ Q, const __half* __restrict__ Kg,
    const __half* __restrict__ V, __half* __restrict__ O, int ldq) {
    extern __shared__ float sm[];
    float* scoresT = sm;
    float* Qs = sm + ASM_Q;
    float* KV = sm + ASM_KV;
    uint32_t* scoresT_u = (uint32_t*)scoresT;
    const uint32_t* Qs_u = (const uint32_t*)Qs;
    const uint32_t* KV_u = (const uint32_t*)KV;

    int tid = threadIdx.x;
    int wid = tid >> 5, lane = tid & 31;
    int g = lane >> 2, c = lane & 3;
    int qt = blockIdx.x;
    int hh = blockIdx.y;
    int sg = blockIdx.z;
    int qbase = sg * SEGLEN + qt * 32;
    int kbase = sg * SEGLEN;
    int colbase = hh * HD;

    {
        int r = tid >> 3, f8 = tid & 7;
        uint4 raw = *(const uint4*)(Q + (size_t)(qbase + r) * ldq + colbase + f8 * 8);
        const __half2* hp = (const __half2*)&raw;
        float* dst = &Qs[r * QPITCH + f8 * 8];
#pragma unroll
        for (int j = 0; j < 4; j++) {
            float2 f = __half22float2(hp[j]);
            dst[2 * j] = f.x * 0.125f;
            dst[2 * j + 1] = f.y * 0.125f;
        }
    }

    // ---- Phase A: S = Q @ K^T ----
    for (int kc = 0; kc < 4; kc++) {
        __syncthreads();
#pragma unroll
        for (int i = 0; i < 4; i++) {
            int s = tid + i * 256;
            int r = s >> 3, f8 = s & 7;
            uint4 raw = *(const uint4*)(Kg + (size_t)(kbase + kc * 128 + r) * ldq + colbase + f8 * 8);
            const __half2* hp = (const __half2*)&raw;
            float* dst = &KV[r * QPITCH + f8 * 8];
#pragma unroll
            for (int j = 0; j < 4; j++) {
                float2 f = __half22float2(hp[j]);
                dst[2 * j] = f.x;
                dst[2 * j + 1] = f.y;
            }
        }
        __syncthreads();

        float accS[2][2][4];
#pragma unroll
        for (int mt = 0; mt < 2; mt++)
#pragma unroll
            for (int nt = 0; nt < 2; nt++)
#pragma unroll
                for (int u = 0; u < 4; u++) accS[mt][nt][u] = 0.f;

#pragma unroll
        for (int ks = 0; ks < 8; ks++) {
            int k0 = ks * 8;
            uint32_t qa[2][4];
#pragma unroll
            for (int mt = 0; mt < 2; mt++) {
                int rm = mt * 16 + g;
                qa[mt][0] = Qs_u[rm * QPITCH + k0 + c];
                qa[mt][1] = Qs_u[(rm + 8) * QPITCH + k0 + c];
                qa[mt][2] = Qs_u[rm * QPITCH + k0 + c + 4];
                qa[mt][3] = Qs_u[(rm + 8) * QPITCH + k0 + c + 4];
            }
#pragma unroll
            for (int nt = 0; nt < 2; nt++) {
                int rk = wid * 16 + nt * 8 + g;
                uint32_t kb[2];
                kb[0] = KV_u[rk * QPITCH + k0 + c];
                kb[1] = KV_u[rk * QPITCH + k0 + c + 4];
#pragma unroll
                for (int mt = 0; mt < 2; mt++)
                    mma_tf32(accS[mt][nt], qa[mt], kb);
            }
        }
#pragma unroll
        for (int mt = 0; mt < 2; mt++)
#pragma unroll
            for (int nt = 0; nt < 2; nt++) {
                int keyg = kc * 128 + wid * 16 + nt * 8 + 2 * c;
                int q0 = mt * 16 + g;
                scoresT[keyg * SP + q0]           = accS[mt][nt][0];
                scoresT[(keyg + 1) * SP + q0]     = accS[mt][nt][1];
                scoresT[keyg * SP + q0 + 8]       = accS[mt][nt][2];
                scoresT[(keyg + 1) * SP + q0 + 8] = accS[mt][nt][3];
            }
    }
    __syncthreads();

    // ---- softmax ----
    {
        int w = wid, l = lane;
        for (int qi = 0; qi < 4; qi++) {
            int q = w + qi * 8;
            float vals[16];
            float m = -1e30f;
#pragma unroll
            for (int s = 0; s < 16; s++) {
                vals[s] = scoresT[(l + s * 32) * SP + q];
                m = fmaxf(m, vals[s]);
            }
#pragma unroll
            for (int o = 16; o > 0; o >>= 1) m = fmaxf(m, __shfl_xor_sync(0xFFFFFFFFu, m, o));
            float sum = 0.f;
#pragma unroll
            for (int s = 0; s < 16; s++) {
                float e = __expf(vals[s] - m);
                vals[s] = e;
                sum += e;
            }
#pragma unroll
            for (int o = 16; o > 0; o >>= 1) sum += __shfl_xor_sync(0xFFFFFFFFu, sum, o);
            float r = 1.f / sum;
#pragma unroll
            for (int s = 0; s < 16; s++)
                scoresT[(l + s * 32) * SP + q] = f2tf_f(vals[s] * r);
        }
    }

    // ---- Phase C: O = P @ V ----
    int mhalf = wid & 1;
    int dq = wid >> 1;
    int q0 = mhalf * 16, d0 = dq * 16;
    float accO[2][4];
#pragma unroll
    for (int nt = 0; nt < 2; nt++)
#pragma unroll
        for (int u = 0; u < 4; u++) accO[nt][u] = 0.f;

    for (int kc = 0; kc < 4; kc++) {
        __syncthreads();
#pragma unroll
        for (int i = 0; i < 4; i++) {
            int s = tid + i * 256;
            int r = s >> 3, f8 = s & 7;
            uint4 raw = *(const uint4*)(V + (size_t)(kbase + kc * 128 + r) * ldq + colbase + f8 * 8);
            const __half2* hp = (const __half2*)&raw;
            int d = f8 * 8;
#pragma unroll
            for (int j = 0; j < 4; j++) {
                float2 f = __half22float2(hp[j]);
                KV[(d + 2 * j) * VPITCH + r]     = f.x;
                KV[(d + 2 * j + 1) * VPITCH + r] = f.y;
            }
        }
        __syncthreads();

#pragma unroll
        for (int ks = 0; ks < 16; ks++) {
            int k0 = ks * 8;
            int keyg = kc * 128 + k0;
            uint32_t pa[4];
            pa[0] = scoresT_u[(keyg + c) * SP + q0 + g];
            pa[1] = scoresT_u[(keyg + c) * SP + q0 + 8 + g];
            pa[2] = scoresT_u[(keyg + c + 4) * SP + q0 + g];
            pa[3] = scoresT_u[(keyg + c + 4) * SP + q0 + 8 + g];
#pragma unroll
            for (int nt = 0; nt < 2; nt++) {
                uint32_t vb[2];
                int dn = d0 + nt * 8 + g;
                vb[0] = KV_u[dn * VPITCH + k0 + c];
                vb[1] = KV_u[dn * VPITCH + k0 + c + 4];
                mma_tf32(accO[nt], pa, vb);
            }
        }
    }

#pragma unroll
    for (int nt = 0; nt < 2; nt++) {
        int dcol = colbase + d0 + nt * 8 + 2 * c;
        __half2* r0 = (__half2*)&O[(size_t)(qbase + q0 + g) * DIM + dcol];
        __half2* r1 = (__half2*)&O[(size_t)(qbase + q0 + 8 + g) * DIM + dcol];
        *r0 = __floats2half2_rn(accO[nt][0], accO[nt][1]);
        *r1 = __floats2half2_rn(accO[nt][2], accO[nt][3]);
    }
}

// ---------------- launch ----------------
extern "C" void kernel_launch(void* const* d_in, const int* in_sizes, int n_in,
                              void* d_out, int out_size) {
    const float* hidden = (const float*)d_in[0];
    const float* Wq = (const float*)d_in[2];
    const float* bq = (const float*)d_in[3];
    const float* Wk = (const float*)d_in[4];
    const float* Wv = (const float*)d_in[5];
    const float* bv = (const float*)d_in[6];
    const float* Wo = (const float*)d_in[7];
    const float* bo = (const float*)d_in[8];
    const float* g1 = (const float*)d_in[9];
    const float* b1 = (const float*)d_in[10];
    const float* Wf1 = (const float*)d_in[11];
    const float* bf1 = (const float*)d_in[12];
    const float* Wf2 = (const float*)d_in[13];
    const float* bf2 = (const float*)d_in[14];
    const float* g2 = (const float*)d_in[15];
    const float* b2 = (const float*)d_in[16];
    float* out = (float*)d_out;

    __half *xln, *qkv, *attnh, *yln, *mid;
    __half *wqkvt, *wot, *wf1t, *wf2t;
    float *h, *bqkv;
    cudaGetSymbolAddress((void**)&xln, g_xln);
    cudaGetSymbolAddress((void**)&qkv, g_qkv);
    cudaGetSymbolAddress((void**)&attnh, g_attnh);
    cudaGetSymbolAddress((void**)&h, g_h);
    cudaGetSymbolAddress((void**)&yln, g_yln);
    cudaGetSymbolAddress((void**)&mid, g_mid);
    cudaGetSymbolAddress((void**)&wqkvt, g_wqkvt);
    cudaGetSymbolAddress((void**)&bqkv, g_bqkv);
    cudaGetSymbolAddress((void**)&wot, g_wot);
    cudaGetSymbolAddress((void**)&wf1t, g_wf1t);
    cudaGetSymbolAddress((void**)&wf2t, g_wf2t);

    const int ATTN_SMEM = ATTN_SMEM_FLOATS * 4;
    cudaFuncSetAttribute(attn_kernel, cudaFuncAttributeMaxDynamicSharedMemorySize, ATTN_SMEM);
    cudaFuncSetAttribute(mma_gemm<EPI_BIAS, 1>, cudaFuncAttributeMaxDynamicSharedMemorySize, GEMM_DSMEM);
    cudaFuncSetAttribute(mma_gemm<EPI_GELU, 1>, cudaFuncAttributeMaxDynamicSharedMemorySize, GEMM_DSMEM);
    cudaFuncSetAttribute(mma_gemm<EPI_BIAS_RES, 0>, cudaFuncAttributeMaxDynamicSharedMemorySize, GEMM_DSMEM);

    dim3 tb(32, 8);
    transpose_k<<<dim3(DIM / 32, DIM / 32), tb>>>(Wq, wqkvt, DIM, DIM, DIM);
    transpose_k<<<dim3(DIM / 32, DIM / 32), tb>>>(Wk, wqkvt + (size_t)DIM * DIM, DIM, DIM, DIM);
    transpose_k<<<dim3(DIM / 32, DIM / 32), tb>>>(Wv, wqkvt + (size_t)2 * DIM * DIM, DIM, DIM, DIM);
    transpose_k<<<dim3(DIM / 32, DIM / 32), tb>>>(Wo, wot, DIM, DIM, DIM);
    transpose_k<<<dim3(FFNDIM / 32, DIM / 32), tb>>>(Wf1, wf1t, DIM, FFNDIM, DIM);
    transpose_k<<<dim3(DIM / 32, FFNDIM / 32), tb>>>(Wf2, wf2t, FFNDIM, DIM, FFNDIM);
    qkvbias_k<<<QKVN / 256, 256>>>(bq, bv, bqkv);

    dim3 gQKV(QKVN / 128, SEQ / 128);
    dim3 gD(DIM / 128, SEQ / 128);
    dim3 gF(FFNDIM / 128, SEQ / 128);

    // LN1 (half out)
    ln_kernel<<<SEQ, 256>>>(hidden, g1, b1, xln);
    // fused QKV GEMM -> half [4096, 3840]
    mma_gemm<EPI_BIAS, 1><<<gQKV, 256, GEMM_DSMEM>>>(xln, wqkvt, bqkv, nullptr, qkv, QKVN, DIM);
    // attention (block-diagonal), half in/out
    attn_kernel<<<dim3(16, NH, 8), 256, ATTN_SMEM>>>(qkv, qkv + DIM, qkv + 2 * DIM, attnh, QKVN);
    // O proj + residual (fp32 out)
    mma_gemm<EPI_BIAS_RES, 0><<<gD, 256, GEMM_DSMEM>>>(attnh, wot, bo, hidden, h, DIM, DIM);
    // LN2 (half out)
    ln_kernel<<<SEQ, 256>>>(h, g2, b2, yln);
    // FFN
    mma_gemm<EPI_GELU, 1><<<gF, 256, GEMM_DSMEM>>>(yln, wf1t, bf1, nullptr, mid, FFNDIM, DIM);
    mma_gemm<EPI_BIAS_RES, 0><<<gD, 256, GEMM_DSMEM>>>(mid, wf2t, bf2, h, out, DIM, FFNDIM);
}